// round 1
// baseline (speedup 1.0000x reference)
#include <cuda_runtime.h>
#include <cuda_bf16.h>
#include <cstdint>

// Problem constants (fixed by the dataset)
#define N_NODES 100000
#define N_EDGES 1600000
#define D_IN    256
#define D_EDGE  16
#define D_OUT   128

// Scratch (allocation-free rule: __device__ globals)
__device__ float g_H[(size_t)N_NODES * D_OUT];     // X @ W_neigh
__device__ float g_acc[(size_t)N_NODES * D_OUT];   // sum over incoming edges of (H[src] + eproj)
__device__ float g_cnt[N_NODES];                   // in-degree (as float)

// ---------------------------------------------------------------------------
// Zero scratch (acc + cnt)
// ---------------------------------------------------------------------------
__global__ void zero_kernel() {
    const int accN4 = (N_NODES * D_OUT) / 4;   // 3,200,000
    const int cntN4 = N_NODES / 4;             // 25,000
    int idx = blockIdx.x * blockDim.x + threadIdx.x;
    int total = accN4 + cntN4;
    if (idx >= total) return;
    if (idx < accN4) {
        ((float4*)g_acc)[idx] = make_float4(0.f, 0.f, 0.f, 0.f);
    } else {
        ((float4*)g_cnt)[idx - accN4] = make_float4(0.f, 0.f, 0.f, 0.f);
    }
}

// ---------------------------------------------------------------------------
// Fused node GEMM: colTile 0 -> g_H = X @ W_neigh
//                  colTile 1 -> out = X @ W_self + b_self
// Classic 128x128x16 fp32 SGEMM, 256 threads, 8x8 per thread.
// ---------------------------------------------------------------------------
#define BM 128
#define BN 128
#define BK 16
#define TM 8
#define TN 8

__global__ __launch_bounds__(256)
void gemm_kernel(const float* __restrict__ X,
                 const float* __restrict__ Wn,
                 const float* __restrict__ Ws,
                 const float* __restrict__ bias,
                 float* __restrict__ out) {
    __shared__ float As[BK][BM + 4];   // padded to break bank conflicts
    __shared__ float Bs[BK][BN];

    const int colTile = blockIdx.x;            // 0: W_neigh -> g_H, 1: W_self -> out
    const int rowBase = blockIdx.y * BM;
    const float* __restrict__ W = (colTile == 0) ? Wn : Ws;

    const int tid = threadIdx.x;
    const int tx = tid & 15;     // 0..15 (cols)
    const int ty = tid >> 4;     // 0..15 (rows)

    // A-loader mapping: 128 rows x 16 cols, float4 per thread, 2 passes
    const int rA = tid >> 2;            // 0..63
    const int cA = (tid & 3) * 4;       // 0,4,8,12
    // B-loader mapping: 16 rows x 128 cols, float4 per thread, 2 passes
    const int rB = tid >> 5;            // 0..7
    const int cB = (tid & 31) * 4;      // 0..124

    float acc[TM][TN];
    #pragma unroll
    for (int m = 0; m < TM; m++)
        #pragma unroll
        for (int n = 0; n < TN; n++)
            acc[m][n] = 0.f;

    for (int k0 = 0; k0 < D_IN; k0 += BK) {
        #pragma unroll
        for (int i = 0; i < 2; i++) {
            int row = rowBase + rA + i * 64;
            float4 v = make_float4(0.f, 0.f, 0.f, 0.f);
            if (row < N_NODES)
                v = *(const float4*)(X + (size_t)row * D_IN + k0 + cA);
            As[cA + 0][rA + i * 64] = v.x;
            As[cA + 1][rA + i * 64] = v.y;
            As[cA + 2][rA + i * 64] = v.z;
            As[cA + 3][rA + i * 64] = v.w;
        }
        #pragma unroll
        for (int i = 0; i < 2; i++) {
            float4 v = *(const float4*)(W + (size_t)(k0 + rB + i * 8) * D_OUT + cB);
            *(float4*)&Bs[rB + i * 8][cB] = v;
        }
        __syncthreads();

        #pragma unroll
        for (int k = 0; k < BK; k++) {
            float a[TM], b[TN];
            float4 a0 = *(const float4*)&As[k][ty * TM];
            float4 a1 = *(const float4*)&As[k][ty * TM + 4];
            a[0]=a0.x; a[1]=a0.y; a[2]=a0.z; a[3]=a0.w;
            a[4]=a1.x; a[5]=a1.y; a[6]=a1.z; a[7]=a1.w;
            float4 b0 = *(const float4*)&Bs[k][tx * TN];
            float4 b1 = *(const float4*)&Bs[k][tx * TN + 4];
            b[0]=b0.x; b[1]=b0.y; b[2]=b0.z; b[3]=b0.w;
            b[4]=b1.x; b[5]=b1.y; b[6]=b1.z; b[7]=b1.w;
            #pragma unroll
            for (int m = 0; m < TM; m++)
                #pragma unroll
                for (int n = 0; n < TN; n++)
                    acc[m][n] = fmaf(a[m], b[n], acc[m][n]);
        }
        __syncthreads();
    }

    float* __restrict__ dstp = (colTile == 0) ? g_H : out;
    #pragma unroll
    for (int m = 0; m < TM; m++) {
        int row = rowBase + ty * TM + m;
        if (row >= N_NODES) continue;
        #pragma unroll
        for (int n = 0; n < TN; n += 4) {
            int col = tx * TN + n;
            float4 v = make_float4(acc[m][n], acc[m][n+1], acc[m][n+2], acc[m][n+3]);
            if (colTile == 1) {
                v.x += bias[col + 0];
                v.y += bias[col + 1];
                v.z += bias[col + 2];
                v.w += bias[col + 3];
            }
            *(float4*)(dstp + (size_t)row * D_OUT + col) = v;
        }
    }
}

// ---------------------------------------------------------------------------
// Edge pass: one warp per edge (grid-stride).
//   val = g_H[src] + X_edge[e] @ W_edge      (128 floats, 4 per lane)
//   red.global.add.v4.f32 into g_acc[dst], lane0 bumps g_cnt[dst].
// W_edge held in registers (16 x float4 per lane).
// ---------------------------------------------------------------------------
__global__ __launch_bounds__(256)
void edge_kernel(const float* __restrict__ Xe,
                 const float* __restrict__ We,     // [16][128]
                 const int*   __restrict__ src,
                 const int*   __restrict__ dst) {
    const int lane = threadIdx.x & 31;
    const int col  = lane * 4;

    // Load this lane's W_edge columns into registers (reused across all edges)
    float4 w[D_EDGE];
    #pragma unroll
    for (int k = 0; k < D_EDGE; k++)
        w[k] = *(const float4*)(We + k * D_OUT + col);

    const int warpId = (blockIdx.x * blockDim.x + threadIdx.x) >> 5;
    const int nWarps = (gridDim.x * blockDim.x) >> 5;

    for (int e = warpId; e < N_EDGES; e += nWarps) {
        const int s = src[e];
        const int d = dst[e];

        // X_edge row (16 floats) — warp-uniform broadcast loads
        const float4 e0 = *(const float4*)(Xe + (size_t)e * D_EDGE + 0);
        const float4 e1 = *(const float4*)(Xe + (size_t)e * D_EDGE + 4);
        const float4 e2 = *(const float4*)(Xe + (size_t)e * D_EDGE + 8);
        const float4 e3 = *(const float4*)(Xe + (size_t)e * D_EDGE + 12);
        float xe[D_EDGE] = {e0.x,e0.y,e0.z,e0.w, e1.x,e1.y,e1.z,e1.w,
                            e2.x,e2.y,e2.z,e2.w, e3.x,e3.y,e3.z,e3.w};

        // Gather projected source features
        float4 v = *(const float4*)(g_H + (size_t)s * D_OUT + col);

        // Edge projection: 4 output cols per lane
        #pragma unroll
        for (int k = 0; k < D_EDGE; k++) {
            v.x = fmaf(xe[k], w[k].x, v.x);
            v.y = fmaf(xe[k], w[k].y, v.y);
            v.z = fmaf(xe[k], w[k].z, v.z);
            v.w = fmaf(xe[k], w[k].w, v.w);
        }

        float* p = g_acc + (size_t)d * D_OUT + col;
        asm volatile("red.global.add.v4.f32 [%0], {%1,%2,%3,%4};"
                     :: "l"(p), "f"(v.x), "f"(v.y), "f"(v.z), "f"(v.w)
                     : "memory");
        if (lane == 0)
            atomicAdd(&g_cnt[d], 1.0f);
    }
}

// ---------------------------------------------------------------------------
// Final combine: out += (cnt>0) ? acc/cnt : 0
// ---------------------------------------------------------------------------
__global__ void final_kernel(float* __restrict__ out) {
    int idx = blockIdx.x * blockDim.x + threadIdx.x;   // one float4 per thread
    const int total = (N_NODES * D_OUT) / 4;           // 3,200,000
    if (idx >= total) return;
    const int n = idx >> 5;           // node (32 float4 per node)
    const float c = g_cnt[n];
    if (c > 0.f) {
        const float inv = 1.0f / c;
        float4 a = ((const float4*)g_acc)[idx];
        float4 o = ((float4*)out)[idx];
        o.x = fmaf(a.x, inv, o.x);
        o.y = fmaf(a.y, inv, o.y);
        o.z = fmaf(a.z, inv, o.z);
        o.w = fmaf(a.w, inv, o.w);
        ((float4*)out)[idx] = o;
    }
}

// ---------------------------------------------------------------------------
// Launch
// ---------------------------------------------------------------------------
extern "C" void kernel_launch(void* const* d_in, const int* in_sizes, int n_in,
                              void* d_out, int out_size) {
    const float* X      = (const float*)d_in[0];
    const float* Xe     = (const float*)d_in[1];
    const float* Wn     = (const float*)d_in[2];
    const float* Ws     = (const float*)d_in[3];
    const float* bias   = (const float*)d_in[4];
    const float* We     = (const float*)d_in[5];
    const int*   src    = (const int*)d_in[6];
    const int*   dst    = (const int*)d_in[7];
    float*       out    = (float*)d_out;

    // 1) zero scratch
    {
        const int total = (N_NODES * D_OUT) / 4 + N_NODES / 4;
        zero_kernel<<<(total + 255) / 256, 256>>>();
    }
    // 2) fused node GEMM (H = X@Wn ; out = X@Ws + b)
    {
        dim3 grid(2, (N_NODES + BM - 1) / BM);
        gemm_kernel<<<grid, 256>>>(X, Wn, Ws, bias, out);
    }
    // 3) edge scatter pass
    {
        edge_kernel<<<4096, 256>>>(Xe, We, src, dst);
    }
    // 4) combine
    {
        const int total = (N_NODES * D_OUT) / 4;
        final_kernel<<<(total + 255) / 256, 256>>>(out);
    }
}

// round 3
// speedup vs baseline: 1.0726x; 1.0726x over previous
#include <cuda_runtime.h>
#include <cuda_bf16.h>
#include <mma.h>
#include <cstdint>

using namespace nvcuda;

// Problem constants (fixed by the dataset)
#define N_NODES 100000
#define N_EDGES 1600000
#define D_IN    256
#define D_EDGE  16
#define D_OUT   128

// Scratch (allocation-free rule: __device__ globals)
__device__ float g_H[(size_t)N_NODES * D_OUT];     // X @ W_neigh
__device__ float g_acc[(size_t)N_NODES * D_OUT];   // sum over incoming edges
__device__ float g_cnt[N_NODES];                   // in-degree (as float)

__device__ __forceinline__ uint32_t pack_bf16(__nv_bfloat16 a, __nv_bfloat16 b) {
    __nv_bfloat162 t(a, b);
    return *reinterpret_cast<uint32_t*>(&t);
}
__device__ __forceinline__ void split_bf16(float x, __nv_bfloat16& hi, __nv_bfloat16& lo) {
    hi = __float2bfloat16(x);
    lo = __float2bfloat16(x - __bfloat162float(hi));
}

// ---------------------------------------------------------------------------
// Zero scratch (acc + cnt)
// ---------------------------------------------------------------------------
__global__ void zero_kernel() {
    const int accN4 = (N_NODES * D_OUT) / 4;
    const int cntN4 = N_NODES / 4;
    int idx = blockIdx.x * blockDim.x + threadIdx.x;
    int total = accN4 + cntN4;
    if (idx >= total) return;
    if (idx < accN4) ((float4*)g_acc)[idx] = make_float4(0.f, 0.f, 0.f, 0.f);
    else             ((float4*)g_cnt)[idx - accN4] = make_float4(0.f, 0.f, 0.f, 0.f);
}

// ---------------------------------------------------------------------------
// Tensor-core node GEMM (wmma bf16, 2-term split for fp32 accuracy):
//   blockIdx.x == 0:  g_H = X @ W_neigh
//   blockIdx.x == 1:  out = X @ W_self        (bias added in final_kernel)
// CTA tile 128x128, 8 warps (4 in M x 2 in N), warp tile 32x64.
// K chunked by 32 through SMEM; 3 HMMA products per fragment (hi*hi+hi*lo+lo*hi).
// ---------------------------------------------------------------------------
#define TILE_M 128
#define KC     32
#define LDA    40     // As leading dim (bf16 elems), row stride 80B (16B-aligned)
#define LDB    136    // Bs leading dim (bf16 elems), row stride 272B (16B-aligned)

__global__ __launch_bounds__(256)
void gemm_wmma_kernel(const float* __restrict__ X,
                      const float* __restrict__ Wn,
                      const float* __restrict__ Ws,
                      float* __restrict__ out) {
    __shared__ __nv_bfloat16 As_hi[TILE_M][LDA];
    __shared__ __nv_bfloat16 As_lo[TILE_M][LDA];
    __shared__ __nv_bfloat16 Bs_hi[KC][LDB];
    __shared__ __nv_bfloat16 Bs_lo[KC][LDB];

    const int tid  = threadIdx.x;
    const int wid  = tid >> 5;
    const int lane = tid & 31;
    const int warp_m = wid & 3;      // 4 warps in M -> 32 rows each
    const int warp_n = wid >> 2;     // 2 warps in N -> 64 cols each

    const int colTile = blockIdx.x;  // 0 -> g_H (Wn), 1 -> out (Ws)
    const int rowBase = blockIdx.y * TILE_M;
    const float* __restrict__ W = colTile ? Ws : Wn;

    wmma::fragment<wmma::accumulator, 16, 16, 16, float> acc[2][4];
    #pragma unroll
    for (int m = 0; m < 2; m++)
        #pragma unroll
        for (int n = 0; n < 4; n++)
            wmma::fill_fragment(acc[m][n], 0.0f);

    // A-loader: 128 rows x 32 cols, 16 floats/thread
    const int arow  = tid >> 1;          // 0..127
    const int acol0 = (tid & 1) * 16;    // 0 or 16
    const int agrow = rowBase + arow;
    // B-loader: 32 rows x 128 cols, 16 floats/thread
    const int brow = tid >> 3;           // 0..31
    const int bq   = tid & 7;            // float4 phase

    for (int k0 = 0; k0 < D_IN; k0 += KC) {
        // ---- A chunk (guarded) ----
        #pragma unroll
        for (int j = 0; j < 4; j++) {
            const int c = acol0 + j * 4;
            float4 v = make_float4(0.f, 0.f, 0.f, 0.f);
            if (agrow < N_NODES)
                v = *(const float4*)(X + (size_t)agrow * D_IN + k0 + c);
            __nv_bfloat16 h0,h1,h2,h3,l0,l1,l2,l3;
            split_bf16(v.x, h0, l0); split_bf16(v.y, h1, l1);
            split_bf16(v.z, h2, l2); split_bf16(v.w, h3, l3);
            *(uint2*)&As_hi[arow][c] = make_uint2(pack_bf16(h0,h1), pack_bf16(h2,h3));
            *(uint2*)&As_lo[arow][c] = make_uint2(pack_bf16(l0,l1), pack_bf16(l2,l3));
        }
        // ---- B chunk ----
        #pragma unroll
        for (int j = 0; j < 4; j++) {
            const int c = (bq + j * 8) * 4;   // 0..124 step 4
            float4 v = *(const float4*)(W + (size_t)(k0 + brow) * D_OUT + c);
            __nv_bfloat16 h0,h1,h2,h3,l0,l1,l2,l3;
            split_bf16(v.x, h0, l0); split_bf16(v.y, h1, l1);
            split_bf16(v.z, h2, l2); split_bf16(v.w, h3, l3);
            *(uint2*)&Bs_hi[brow][c] = make_uint2(pack_bf16(h0,h1), pack_bf16(h2,h3));
            *(uint2*)&Bs_lo[brow][c] = make_uint2(pack_bf16(l0,l1), pack_bf16(l2,l3));
        }
        __syncthreads();

        #pragma unroll
        for (int ks = 0; ks < KC / 16; ks++) {
            wmma::fragment<wmma::matrix_a, 16, 16, 16, __nv_bfloat16, wmma::row_major> a_hi[2], a_lo[2];
            #pragma unroll
            for (int m = 0; m < 2; m++) {
                wmma::load_matrix_sync(a_hi[m], &As_hi[warp_m * 32 + m * 16][ks * 16], LDA);
                wmma::load_matrix_sync(a_lo[m], &As_lo[warp_m * 32 + m * 16][ks * 16], LDA);
            }
            #pragma unroll
            for (int n = 0; n < 4; n++) {
                wmma::fragment<wmma::matrix_b, 16, 16, 16, __nv_bfloat16, wmma::row_major> b_hi, b_lo;
                wmma::load_matrix_sync(b_hi, &Bs_hi[ks * 16][warp_n * 64 + n * 16], LDB);
                wmma::load_matrix_sync(b_lo, &Bs_lo[ks * 16][warp_n * 64 + n * 16], LDB);
                #pragma unroll
                for (int m = 0; m < 2; m++) {
                    wmma::mma_sync(acc[m][n], a_hi[m], b_hi, acc[m][n]);
                    wmma::mma_sync(acc[m][n], a_hi[m], b_lo, acc[m][n]);
                    wmma::mma_sync(acc[m][n], a_lo[m], b_hi, acc[m][n]);
                }
            }
        }
        __syncthreads();
    }

    // ---- Epilogue ----
    float* __restrict__ dstbase = colTile ? out : g_H;
    if (rowBase + TILE_M <= N_NODES) {
        // Full tile: direct fragment store to global.
        #pragma unroll
        for (int m = 0; m < 2; m++)
            #pragma unroll
            for (int n = 0; n < 4; n++) {
                float* p = dstbase + (size_t)(rowBase + warp_m * 32 + m * 16) * D_OUT
                                   + warp_n * 64 + n * 16;
                wmma::store_matrix_sync(p, acc[m][n], D_OUT, wmma::mem_row_major);
            }
    } else {
        // Boundary tile: stage each 16x16 fragment in smem, guarded copy.
        __syncthreads();                      // done with As/Bs
        float* stage = (float*)&As_hi[0][0] + wid * 256;   // 16x16 per warp
        #pragma unroll
        for (int m = 0; m < 2; m++)
            #pragma unroll
            for (int n = 0; n < 4; n++) {
                wmma::store_matrix_sync(stage, acc[m][n], 16, wmma::mem_row_major);
                __syncwarp();
                const int r = lane >> 1;
                const int c = (lane & 1) * 8;
                const int grow = rowBase + warp_m * 32 + m * 16 + r;
                if (grow < N_NODES) {
                    float* p = dstbase + (size_t)grow * D_OUT + warp_n * 64 + n * 16 + c;
                    *(float4*)(p + 0) = *(float4*)(stage + r * 16 + c + 0);
                    *(float4*)(p + 4) = *(float4*)(stage + r * 16 + c + 4);
                }
                __syncwarp();
            }
    }
}

// ---------------------------------------------------------------------------
// Edge pass: one warp per edge (grid-stride).
//   val = g_H[src] + X_edge[e] @ W_edge      (128 floats, 4 per lane)
//   red.global.add.v4.f32 into g_acc[dst], lane0 bumps g_cnt[dst].
// ---------------------------------------------------------------------------
__global__ __launch_bounds__(256)
void edge_kernel(const float* __restrict__ Xe,
                 const float* __restrict__ We,     // [16][128]
                 const int*   __restrict__ src,
                 const int*   __restrict__ dst) {
    const int lane = threadIdx.x & 31;
    const int col  = lane * 4;

    float4 w[D_EDGE];
    #pragma unroll
    for (int k = 0; k < D_EDGE; k++)
        w[k] = *(const float4*)(We + k * D_OUT + col);

    const int warpId = (blockIdx.x * blockDim.x + threadIdx.x) >> 5;
    const int nWarps = (gridDim.x * blockDim.x) >> 5;

    for (int e = warpId; e < N_EDGES; e += nWarps) {
        const int s = src[e];
        const int d = dst[e];

        const float4 e0 = *(const float4*)(Xe + (size_t)e * D_EDGE + 0);
        const float4 e1 = *(const float4*)(Xe + (size_t)e * D_EDGE + 4);
        const float4 e2 = *(const float4*)(Xe + (size_t)e * D_EDGE + 8);
        const float4 e3 = *(const float4*)(Xe + (size_t)e * D_EDGE + 12);
        float xe[D_EDGE] = {e0.x,e0.y,e0.z,e0.w, e1.x,e1.y,e1.z,e1.w,
                            e2.x,e2.y,e2.z,e2.w, e3.x,e3.y,e3.z,e3.w};

        float4 v = *(const float4*)(g_H + (size_t)s * D_OUT + col);

        #pragma unroll
        for (int k = 0; k < D_EDGE; k++) {
            v.x = fmaf(xe[k], w[k].x, v.x);
            v.y = fmaf(xe[k], w[k].y, v.y);
            v.z = fmaf(xe[k], w[k].z, v.z);
            v.w = fmaf(xe[k], w[k].w, v.w);
        }

        float* p = g_acc + (size_t)d * D_OUT + col;
        asm volatile("red.global.add.v4.f32 [%0], {%1,%2,%3,%4};"
                     :: "l"(p), "f"(v.x), "f"(v.y), "f"(v.z), "f"(v.w)
                     : "memory");
        if (lane == 0)
            atomicAdd(&g_cnt[d], 1.0f);
    }
}

// ---------------------------------------------------------------------------
// Final combine: out += bias + (cnt>0 ? acc/cnt : 0)
// ---------------------------------------------------------------------------
__global__ void final_kernel(float* __restrict__ out, const float* __restrict__ bias) {
    int idx = blockIdx.x * blockDim.x + threadIdx.x;
    const int total = (N_NODES * D_OUT) / 4;
    if (idx >= total) return;
    const int n = idx >> 5;
    const float c = g_cnt[n];
    const float4 b = ((const float4*)bias)[idx & 31];
    float4 o = ((float4*)out)[idx];
    o.x += b.x; o.y += b.y; o.z += b.z; o.w += b.w;
    if (c > 0.f) {
        const float inv = 1.0f / c;
        float4 a = ((const float4*)g_acc)[idx];
        o.x = fmaf(a.x, inv, o.x);
        o.y = fmaf(a.y, inv, o.y);
        o.z = fmaf(a.z, inv, o.z);
        o.w = fmaf(a.w, inv, o.w);
    }
    ((float4*)out)[idx] = o;
}

// ---------------------------------------------------------------------------
// Launch
// ---------------------------------------------------------------------------
extern "C" void kernel_launch(void* const* d_in, const int* in_sizes, int n_in,
                              void* d_out, int out_size) {
    const float* X    = (const float*)d_in[0];
    const float* Xe   = (const float*)d_in[1];
    const float* Wn   = (const float*)d_in[2];
    const float* Ws   = (const float*)d_in[3];
    const float* bias = (const float*)d_in[4];
    const float* We   = (const float*)d_in[5];
    const int*   src  = (const int*)d_in[6];
    const int*   dst  = (const int*)d_in[7];
    float*       out  = (float*)d_out;

    // 1) zero scratch
    {
        const int total = (N_NODES * D_OUT) / 4 + N_NODES / 4;
        zero_kernel<<<(total + 255) / 256, 256>>>();
    }
    // 2) tensor-core node GEMMs: g_H = X@Wn ; out = X@Ws
    {
        dim3 grid(2, (N_NODES + TILE_M - 1) / TILE_M);   // (2, 782)
        gemm_wmma_kernel<<<grid, 256>>>(X, Wn, Ws, out);
    }
    // 3) edge scatter pass
    edge_kernel<<<4096, 256>>>(Xe, We, src, dst);
    // 4) combine (+bias)
    {
        const int total = (N_NODES * D_OUT) / 4;
        final_kernel<<<(total + 255) / 256, 256>>>(out, bias);
    }
}

// round 4
// speedup vs baseline: 2.6784x; 2.4972x over previous
#include <cuda_runtime.h>
#include <cuda_bf16.h>
#include <mma.h>
#include <cstdint>

using namespace nvcuda;

#define N_NODES 100000
#define N_EDGES 1600000
#define D_IN    256
#define D_EDGE  16
#define D_OUT   128

#define SCAN_BLK  1024
#define SCAN_NB   ((N_NODES + SCAN_BLK - 1) / SCAN_BLK)   // 98

// Scratch (allocation-free rule: __device__ globals)
__device__ float              g_H[(size_t)N_NODES * D_OUT];   // X @ W_neigh
__device__ int                g_deg[N_NODES];                 // in-degree
__device__ int                g_off[N_NODES];                 // CSR offsets (exclusive)
__device__ int                g_cursor[N_NODES];              // scatter cursors
__device__ int                g_bsum[SCAN_NB];                // block sums for scan
__device__ unsigned long long g_list[N_EDGES];                // packed (edge<<32 | src)

__device__ __forceinline__ uint32_t pack_bf16(__nv_bfloat16 a, __nv_bfloat16 b) {
    __nv_bfloat162 t(a, b);
    return *reinterpret_cast<uint32_t*>(&t);
}
__device__ __forceinline__ void split_bf16(float x, __nv_bfloat16& hi, __nv_bfloat16& lo) {
    hi = __float2bfloat16(x);
    lo = __float2bfloat16(x - __bfloat162float(hi));
}

// ---------------------------------------------------------------------------
// CSR construction
// ---------------------------------------------------------------------------
__global__ void zero_deg_kernel() {
    int i = blockIdx.x * blockDim.x + threadIdx.x;
    if (i < N_NODES) g_deg[i] = 0;
}

__global__ void hist_kernel(const int* __restrict__ dst) {
    int e = blockIdx.x * blockDim.x + threadIdx.x;
    if (e < N_EDGES) atomicAdd(&g_deg[dst[e]], 1);
}

// Per-block inclusive scan (Hillis-Steele); writes local-exclusive to g_off,
// block total to g_bsum.
__global__ __launch_bounds__(SCAN_BLK)
void scanA_kernel() {
    __shared__ int s[SCAN_BLK];
    const int t = threadIdx.x;
    const int i = blockIdx.x * SCAN_BLK + t;
    const int d = (i < N_NODES) ? g_deg[i] : 0;
    s[t] = d;
    __syncthreads();
    #pragma unroll
    for (int off = 1; off < SCAN_BLK; off <<= 1) {
        int v = (t >= off) ? s[t - off] : 0;
        __syncthreads();
        s[t] += v;
        __syncthreads();
    }
    if (i < N_NODES) g_off[i] = s[t] - d;      // local exclusive
    if (t == SCAN_BLK - 1) g_bsum[blockIdx.x] = s[t];
}

__global__ void scanB_kernel() {
    if (threadIdx.x == 0 && blockIdx.x == 0) {
        int run = 0;
        for (int b = 0; b < SCAN_NB; ++b) {
            int v = g_bsum[b];
            g_bsum[b] = run;
            run += v;
        }
    }
}

__global__ __launch_bounds__(SCAN_BLK)
void scanC_kernel() {
    const int i = blockIdx.x * SCAN_BLK + threadIdx.x;
    if (i < N_NODES) {
        int o = g_off[i] + g_bsum[blockIdx.x];
        g_off[i] = o;
        g_cursor[i] = o;
    }
}

__global__ void scatter_kernel(const int* __restrict__ src,
                               const int* __restrict__ dst) {
    int e = blockIdx.x * blockDim.x + threadIdx.x;
    if (e >= N_EDGES) return;
    const int d = dst[e];
    const int pos = atomicAdd(&g_cursor[d], 1);
    g_list[pos] = ((unsigned long long)(unsigned)e << 32) | (unsigned)src[e];
}

// ---------------------------------------------------------------------------
// Tensor-core node GEMM (wmma bf16, 2-term split for fp32 accuracy):
//   blockIdx.x == 0:  g_H = X @ W_neigh
//   blockIdx.x == 1:  out = X @ W_self      (bias added in aggregate)
// ---------------------------------------------------------------------------
#define TILE_M 128
#define KC     32
#define LDA    40
#define LDB    136

__global__ __launch_bounds__(256)
void gemm_wmma_kernel(const float* __restrict__ X,
                      const float* __restrict__ Wn,
                      const float* __restrict__ Ws,
                      float* __restrict__ out) {
    __shared__ __nv_bfloat16 As_hi[TILE_M][LDA];
    __shared__ __nv_bfloat16 As_lo[TILE_M][LDA];
    __shared__ __nv_bfloat16 Bs_hi[KC][LDB];
    __shared__ __nv_bfloat16 Bs_lo[KC][LDB];

    const int tid  = threadIdx.x;
    const int wid  = tid >> 5;
    const int lane = tid & 31;
    const int warp_m = wid & 3;
    const int warp_n = wid >> 2;

    const int colTile = blockIdx.x;
    const int rowBase = blockIdx.y * TILE_M;
    const float* __restrict__ W = colTile ? Ws : Wn;

    wmma::fragment<wmma::accumulator, 16, 16, 16, float> acc[2][4];
    #pragma unroll
    for (int m = 0; m < 2; m++)
        #pragma unroll
        for (int n = 0; n < 4; n++)
            wmma::fill_fragment(acc[m][n], 0.0f);

    const int arow  = tid >> 1;
    const int acol0 = (tid & 1) * 16;
    const int agrow = rowBase + arow;
    const int brow = tid >> 3;
    const int bq   = tid & 7;

    for (int k0 = 0; k0 < D_IN; k0 += KC) {
        #pragma unroll
        for (int j = 0; j < 4; j++) {
            const int c = acol0 + j * 4;
            float4 v = make_float4(0.f, 0.f, 0.f, 0.f);
            if (agrow < N_NODES)
                v = *(const float4*)(X + (size_t)agrow * D_IN + k0 + c);
            __nv_bfloat16 h0,h1,h2,h3,l0,l1,l2,l3;
            split_bf16(v.x, h0, l0); split_bf16(v.y, h1, l1);
            split_bf16(v.z, h2, l2); split_bf16(v.w, h3, l3);
            *(uint2*)&As_hi[arow][c] = make_uint2(pack_bf16(h0,h1), pack_bf16(h2,h3));
            *(uint2*)&As_lo[arow][c] = make_uint2(pack_bf16(l0,l1), pack_bf16(l2,l3));
        }
        #pragma unroll
        for (int j = 0; j < 4; j++) {
            const int c = (bq + j * 8) * 4;
            float4 v = *(const float4*)(W + (size_t)(k0 + brow) * D_OUT + c);
            __nv_bfloat16 h0,h1,h2,h3,l0,l1,l2,l3;
            split_bf16(v.x, h0, l0); split_bf16(v.y, h1, l1);
            split_bf16(v.z, h2, l2); split_bf16(v.w, h3, l3);
            *(uint2*)&Bs_hi[brow][c] = make_uint2(pack_bf16(h0,h1), pack_bf16(h2,h3));
            *(uint2*)&Bs_lo[brow][c] = make_uint2(pack_bf16(l0,l1), pack_bf16(l2,l3));
        }
        __syncthreads();

        #pragma unroll
        for (int ks = 0; ks < KC / 16; ks++) {
            wmma::fragment<wmma::matrix_a, 16, 16, 16, __nv_bfloat16, wmma::row_major> a_hi[2], a_lo[2];
            #pragma unroll
            for (int m = 0; m < 2; m++) {
                wmma::load_matrix_sync(a_hi[m], &As_hi[warp_m * 32 + m * 16][ks * 16], LDA);
                wmma::load_matrix_sync(a_lo[m], &As_lo[warp_m * 32 + m * 16][ks * 16], LDA);
            }
            #pragma unroll
            for (int n = 0; n < 4; n++) {
                wmma::fragment<wmma::matrix_b, 16, 16, 16, __nv_bfloat16, wmma::row_major> b_hi, b_lo;
                wmma::load_matrix_sync(b_hi, &Bs_hi[ks * 16][warp_n * 64 + n * 16], LDB);
                wmma::load_matrix_sync(b_lo, &Bs_lo[ks * 16][warp_n * 64 + n * 16], LDB);
                #pragma unroll
                for (int m = 0; m < 2; m++) {
                    wmma::mma_sync(acc[m][n], a_hi[m], b_hi, acc[m][n]);
                    wmma::mma_sync(acc[m][n], a_hi[m], b_lo, acc[m][n]);
                    wmma::mma_sync(acc[m][n], a_lo[m], b_hi, acc[m][n]);
                }
            }
        }
        __syncthreads();
    }

    float* __restrict__ dstbase = colTile ? out : g_H;
    if (rowBase + TILE_M <= N_NODES) {
        #pragma unroll
        for (int m = 0; m < 2; m++)
            #pragma unroll
            for (int n = 0; n < 4; n++) {
                float* p = dstbase + (size_t)(rowBase + warp_m * 32 + m * 16) * D_OUT
                                   + warp_n * 64 + n * 16;
                wmma::store_matrix_sync(p, acc[m][n], D_OUT, wmma::mem_row_major);
            }
    } else {
        __syncthreads();
        float* stage = (float*)&As_hi[0][0] + wid * 256;
        #pragma unroll
        for (int m = 0; m < 2; m++)
            #pragma unroll
            for (int n = 0; n < 4; n++) {
                wmma::store_matrix_sync(stage, acc[m][n], 16, wmma::mem_row_major);
                __syncwarp();
                const int r = lane >> 1;
                const int c = (lane & 1) * 8;
                const int grow = rowBase + warp_m * 32 + m * 16 + r;
                if (grow < N_NODES) {
                    float* p = dstbase + (size_t)grow * D_OUT + warp_n * 64 + n * 16 + c;
                    *(float4*)(p + 0) = *(float4*)(stage + r * 16 + c + 0);
                    *(float4*)(p + 4) = *(float4*)(stage + r * 16 + c + 4);
                }
                __syncwarp();
            }
    }
}

// ---------------------------------------------------------------------------
// Aggregate: one warp per dst node (grid-stride). Atomic-free.
//   out[d] += bias + ( sum_e H[src_e] + (sum_e Xe_e) @ We ) / deg[d]
// 2-edge software pipelining; lanes 0-15 / 16-31 split the pair's Xe rows.
// ---------------------------------------------------------------------------
__global__ __launch_bounds__(256)
void aggregate_kernel(const float* __restrict__ Xe,
                      const float* __restrict__ We,    // [16][128]
                      const float* __restrict__ bias,
                      float* __restrict__ out) {
    const int lane = threadIdx.x & 31;
    const int col  = lane * 4;

    float4 w[D_EDGE];
    #pragma unroll
    for (int k = 0; k < D_EDGE; k++)
        w[k] = *(const float4*)(We + k * D_OUT + col);
    const float4 b = *(const float4*)(bias + col);

    const int warpId = (blockIdx.x * blockDim.x + threadIdx.x) >> 5;
    const int nWarps = (gridDim.x * blockDim.x) >> 5;

    for (int d = warpId; d < N_NODES; d += nWarps) {
        const int start = g_off[d];
        const int c     = g_deg[d];

        float4 h = make_float4(0.f, 0.f, 0.f, 0.f);
        float xacc = 0.f;      // lane k and k+16 each hold partials of coord k

        int i = 0;
        for (; i + 2 <= c; i += 2) {
            const unsigned long long pe0 = g_list[start + i];
            const unsigned long long pe1 = g_list[start + i + 1];
            const int s0 = (int)(pe0 & 0xFFFFFFFFu);
            const int s1 = (int)(pe1 & 0xFFFFFFFFu);
            const int e0 = (int)(pe0 >> 32);
            const int e1 = (int)(pe1 >> 32);

            const float4 h0 = *(const float4*)(g_H + (size_t)s0 * D_OUT + col);
            const float4 h1 = *(const float4*)(g_H + (size_t)s1 * D_OUT + col);
            const float xv = (lane < 16) ? Xe[(size_t)e0 * D_EDGE + lane]
                                         : Xe[(size_t)e1 * D_EDGE + (lane - 16)];
            h.x += h0.x + h1.x;
            h.y += h0.y + h1.y;
            h.z += h0.z + h1.z;
            h.w += h0.w + h1.w;
            xacc += xv;
        }
        if (i < c) {
            const unsigned long long pe = g_list[start + i];
            const int s = (int)(pe & 0xFFFFFFFFu);
            const int e = (int)(pe >> 32);
            const float4 hv = *(const float4*)(g_H + (size_t)s * D_OUT + col);
            h.x += hv.x; h.y += hv.y; h.z += hv.z; h.w += hv.w;
            if (lane < 16) xacc += Xe[(size_t)e * D_EDGE + lane];
        }

        float4 o = *(const float4*)(out + (size_t)d * D_OUT + col);
        o.x += b.x; o.y += b.y; o.z += b.z; o.w += b.w;

        if (c > 0) {
            float4 p = make_float4(0.f, 0.f, 0.f, 0.f);
            #pragma unroll
            for (int k = 0; k < D_EDGE; k++) {
                const float xk = __shfl_sync(0xFFFFFFFFu, xacc, k) +
                                 __shfl_sync(0xFFFFFFFFu, xacc, k + 16);
                p.x = fmaf(xk, w[k].x, p.x);
                p.y = fmaf(xk, w[k].y, p.y);
                p.z = fmaf(xk, w[k].z, p.z);
                p.w = fmaf(xk, w[k].w, p.w);
            }
            const float inv = 1.0f / (float)c;
            o.x = fmaf(h.x + p.x, inv, o.x);
            o.y = fmaf(h.y + p.y, inv, o.y);
            o.z = fmaf(h.z + p.z, inv, o.z);
            o.w = fmaf(h.w + p.w, inv, o.w);
        }
        *(float4*)(out + (size_t)d * D_OUT + col) = o;
    }
}

// ---------------------------------------------------------------------------
// Launch
// ---------------------------------------------------------------------------
extern "C" void kernel_launch(void* const* d_in, const int* in_sizes, int n_in,
                              void* d_out, int out_size) {
    const float* X    = (const float*)d_in[0];
    const float* Xe   = (const float*)d_in[1];
    const float* Wn   = (const float*)d_in[2];
    const float* Ws   = (const float*)d_in[3];
    const float* bias = (const float*)d_in[4];
    const float* We   = (const float*)d_in[5];
    const int*   src  = (const int*)d_in[6];
    const int*   dst  = (const int*)d_in[7];
    float*       out  = (float*)d_out;

    // CSR build
    zero_deg_kernel<<<(N_NODES + 255) / 256, 256>>>();
    hist_kernel<<<(N_EDGES + 255) / 256, 256>>>(dst);
    scanA_kernel<<<SCAN_NB, SCAN_BLK>>>();
    scanB_kernel<<<1, 32>>>();
    scanC_kernel<<<SCAN_NB, SCAN_BLK>>>();
    scatter_kernel<<<(N_EDGES + 255) / 256, 256>>>(src, dst);

    // Node GEMMs: g_H = X@Wn ; out = X@Ws
    {
        dim3 grid(2, (N_NODES + TILE_M - 1) / TILE_M);
        gemm_wmma_kernel<<<grid, 256>>>(X, Wn, Ws, out);
    }

    // Gather aggregation (fuses mean, edge projection, bias, final combine)
    aggregate_kernel<<<2048, 256>>>(Xe, We, bias, out);
}

// round 5
// speedup vs baseline: 2.8102x; 1.0492x over previous
#include <cuda_runtime.h>
#include <cuda_bf16.h>
#include <mma.h>
#include <cstdint>

using namespace nvcuda;

#define N_NODES 100000
#define N_EDGES 1600000
#define D_IN    256
#define D_EDGE  16
#define D_OUT   128

#define SCAN_BLK  1024
#define SCAN_NB   ((N_NODES + SCAN_BLK - 1) / SCAN_BLK)   // 98

// Scratch (allocation-free rule: __device__ globals)
__device__ float              g_H[(size_t)N_NODES * D_OUT];   // X @ W_neigh
__device__ int                g_deg[N_NODES];                 // in-degree
__device__ int                g_off[N_NODES];                 // CSR offsets (exclusive)
__device__ int                g_cursor[N_NODES];              // scatter cursors
__device__ int                g_bsum[SCAN_NB];                // block sums for scan
__device__ unsigned long long g_list[N_EDGES];                // packed (edge<<32 | src)

__device__ __forceinline__ uint32_t pack_bf16(__nv_bfloat16 a, __nv_bfloat16 b) {
    __nv_bfloat162 t(a, b);
    return *reinterpret_cast<uint32_t*>(&t);
}
__device__ __forceinline__ void split_bf16(float x, __nv_bfloat16& hi, __nv_bfloat16& lo) {
    hi = __float2bfloat16(x);
    lo = __float2bfloat16(x - __bfloat162float(hi));
}

// ---------------------------------------------------------------------------
// CSR construction
// ---------------------------------------------------------------------------
__global__ void zero_deg_kernel() {
    int i = blockIdx.x * blockDim.x + threadIdx.x;
    if (i < N_NODES) g_deg[i] = 0;
}

__global__ void hist_kernel(const int* __restrict__ dst) {
    int e = blockIdx.x * blockDim.x + threadIdx.x;
    if (e < N_EDGES) atomicAdd(&g_deg[dst[e]], 1);
}

__global__ __launch_bounds__(SCAN_BLK)
void scanA_kernel() {
    __shared__ int s[SCAN_BLK];
    const int t = threadIdx.x;
    const int i = blockIdx.x * SCAN_BLK + t;
    const int d = (i < N_NODES) ? g_deg[i] : 0;
    s[t] = d;
    __syncthreads();
    #pragma unroll
    for (int off = 1; off < SCAN_BLK; off <<= 1) {
        int v = (t >= off) ? s[t - off] : 0;
        __syncthreads();
        s[t] += v;
        __syncthreads();
    }
    if (i < N_NODES) g_off[i] = s[t] - d;      // local exclusive
    if (t == SCAN_BLK - 1) g_bsum[blockIdx.x] = s[t];
}

// Parallel exclusive scan of the 98 block sums (one 128-thread block).
__global__ __launch_bounds__(128)
void scanB_kernel() {
    __shared__ int s[128];
    const int t = threadIdx.x;
    const int v = (t < SCAN_NB) ? g_bsum[t] : 0;
    s[t] = v;
    __syncthreads();
    #pragma unroll
    for (int off = 1; off < 128; off <<= 1) {
        int u = (t >= off) ? s[t - off] : 0;
        __syncthreads();
        s[t] += u;
        __syncthreads();
    }
    if (t < SCAN_NB) g_bsum[t] = s[t] - v;     // exclusive
}

__global__ __launch_bounds__(SCAN_BLK)
void scanC_kernel() {
    const int i = blockIdx.x * SCAN_BLK + threadIdx.x;
    if (i < N_NODES) {
        int o = g_off[i] + g_bsum[blockIdx.x];
        g_off[i] = o;
        g_cursor[i] = o;
    }
}

__global__ void scatter_kernel(const int* __restrict__ src,
                               const int* __restrict__ dst) {
    int e = blockIdx.x * blockDim.x + threadIdx.x;
    if (e >= N_EDGES) return;
    const int d = dst[e];
    const int pos = atomicAdd(&g_cursor[d], 1);
    g_list[pos] = ((unsigned long long)(unsigned)e << 32) | (unsigned)src[e];
}

// ---------------------------------------------------------------------------
// Fused tensor-core node GEMM (wmma bf16, 2-term split):
//   D[128 x 256] = X_tile @ [Wn | Ws];  cols 0-127 -> g_H, 128-255 -> out.
// 512 threads (16 warps, 4x4), warp tile 32x64, register-prefetch pipeline.
// ---------------------------------------------------------------------------
#define TILE_M 128
#define KC     32
#define NCHUNK (D_IN / KC)   // 8
#define LDA    40            // As row stride (bf16), 80B
#define LDB    264           // Bs row stride (bf16), 528B
#define OFF_AS_HI 0
#define OFF_AS_LO 10240
#define OFF_BS_HI 20480
#define OFF_BS_LO 37376
#define GEMM_SMEM 54272

__global__ __launch_bounds__(512)
void gemm_fused_kernel(const float* __restrict__ X,
                       const float* __restrict__ Wn,
                       const float* __restrict__ Ws,
                       float* __restrict__ out) {
    extern __shared__ char smem[];
    __nv_bfloat16* As_hi = (__nv_bfloat16*)(smem + OFF_AS_HI);
    __nv_bfloat16* As_lo = (__nv_bfloat16*)(smem + OFF_AS_LO);
    __nv_bfloat16* Bs_hi = (__nv_bfloat16*)(smem + OFF_BS_HI);
    __nv_bfloat16* Bs_lo = (__nv_bfloat16*)(smem + OFF_BS_LO);

    const int tid  = threadIdx.x;
    const int wid  = tid >> 5;
    const int lane = tid & 31;
    const int warp_m = wid & 3;      // 4 warps in M (32 rows each)
    const int warp_n = wid >> 2;     // 4 warps in N (64 cols each)
    const int rowBase = blockIdx.x * TILE_M;

    // A loader: 128 rows x 32 cols, 8 floats (2 float4) per thread
    const int arow  = tid >> 2;
    const int acol  = (tid & 3) * 8;
    const int agrow = rowBase + arow;
    // B loader: 32 rows x 256 cols, 16 floats (4 float4) per thread
    const int brow = tid >> 4;           // 0..31
    const int bcol = (tid & 15) * 16;    // 0..240
    const float* __restrict__ Wsel = (bcol < 128) ? Wn : Ws;
    const int wcol = bcol & 127;

    wmma::fragment<wmma::accumulator, 16, 16, 16, float> acc[2][4];
    #pragma unroll
    for (int m = 0; m < 2; m++)
        #pragma unroll
        for (int n = 0; n < 4; n++)
            wmma::fill_fragment(acc[m][n], 0.0f);

    float4 pa[2], pb[4];

    // Prologue: load chunk 0
    #pragma unroll
    for (int j = 0; j < 2; j++)
        pa[j] = (agrow < N_NODES)
              ? *(const float4*)(X + (size_t)agrow * D_IN + acol + j * 4)
              : make_float4(0.f, 0.f, 0.f, 0.f);
    #pragma unroll
    for (int j = 0; j < 4; j++)
        pb[j] = *(const float4*)(Wsel + (size_t)brow * D_OUT + wcol + j * 4);

    for (int c = 0; c < NCHUNK; ++c) {
        // ---- Convert prefetched regs -> smem bf16 hi/lo ----
        #pragma unroll
        for (int j = 0; j < 2; j++) {
            __nv_bfloat16 h0,h1,h2,h3,l0,l1,l2,l3;
            split_bf16(pa[j].x, h0, l0); split_bf16(pa[j].y, h1, l1);
            split_bf16(pa[j].z, h2, l2); split_bf16(pa[j].w, h3, l3);
            const int o = arow * LDA + acol + j * 4;
            *(uint2*)(As_hi + o) = make_uint2(pack_bf16(h0,h1), pack_bf16(h2,h3));
            *(uint2*)(As_lo + o) = make_uint2(pack_bf16(l0,l1), pack_bf16(l2,l3));
        }
        #pragma unroll
        for (int j = 0; j < 4; j++) {
            __nv_bfloat16 h0,h1,h2,h3,l0,l1,l2,l3;
            split_bf16(pb[j].x, h0, l0); split_bf16(pb[j].y, h1, l1);
            split_bf16(pb[j].z, h2, l2); split_bf16(pb[j].w, h3, l3);
            const int o = brow * LDB + bcol + j * 4;
            *(uint2*)(Bs_hi + o) = make_uint2(pack_bf16(h0,h1), pack_bf16(h2,h3));
            *(uint2*)(Bs_lo + o) = make_uint2(pack_bf16(l0,l1), pack_bf16(l2,l3));
        }
        __syncthreads();

        // ---- Prefetch next chunk (overlaps with MMAs below) ----
        if (c + 1 < NCHUNK) {
            const int k0 = (c + 1) * KC;
            #pragma unroll
            for (int j = 0; j < 2; j++)
                pa[j] = (agrow < N_NODES)
                      ? *(const float4*)(X + (size_t)agrow * D_IN + k0 + acol + j * 4)
                      : make_float4(0.f, 0.f, 0.f, 0.f);
            #pragma unroll
            for (int j = 0; j < 4; j++)
                pb[j] = *(const float4*)(Wsel + (size_t)(k0 + brow) * D_OUT + wcol + j * 4);
        }

        // ---- MMAs on this chunk ----
        #pragma unroll
        for (int ks = 0; ks < KC / 16; ks++) {
            wmma::fragment<wmma::matrix_a, 16, 16, 16, __nv_bfloat16, wmma::row_major> a_hi[2], a_lo[2];
            #pragma unroll
            for (int m = 0; m < 2; m++) {
                wmma::load_matrix_sync(a_hi[m], As_hi + (warp_m * 32 + m * 16) * LDA + ks * 16, LDA);
                wmma::load_matrix_sync(a_lo[m], As_lo + (warp_m * 32 + m * 16) * LDA + ks * 16, LDA);
            }
            #pragma unroll
            for (int n = 0; n < 4; n++) {
                wmma::fragment<wmma::matrix_b, 16, 16, 16, __nv_bfloat16, wmma::row_major> b_hi, b_lo;
                wmma::load_matrix_sync(b_hi, Bs_hi + (ks * 16) * LDB + warp_n * 64 + n * 16, LDB);
                wmma::load_matrix_sync(b_lo, Bs_lo + (ks * 16) * LDB + warp_n * 64 + n * 16, LDB);
                #pragma unroll
                for (int m = 0; m < 2; m++) {
                    wmma::mma_sync(acc[m][n], a_hi[m], b_hi, acc[m][n]);
                    wmma::mma_sync(acc[m][n], a_hi[m], b_lo, acc[m][n]);
                    wmma::mma_sync(acc[m][n], a_lo[m], b_hi, acc[m][n]);
                }
            }
        }
        __syncthreads();
    }

    // ---- Epilogue: cols 0-127 -> g_H, cols 128-255 -> out ----
    if (rowBase + TILE_M <= N_NODES) {
        #pragma unroll
        for (int m = 0; m < 2; m++)
            #pragma unroll
            for (int n = 0; n < 4; n++) {
                const int row  = rowBase + warp_m * 32 + m * 16;
                const int col  = warp_n * 64 + n * 16;
                float* p = (col < 128)
                         ? g_H + (size_t)row * D_OUT + col
                         : out + (size_t)row * D_OUT + (col - 128);
                wmma::store_matrix_sync(p, acc[m][n], D_OUT, wmma::mem_row_major);
            }
    } else {
        // Boundary tile: stage 16x16 fragments in smem, guarded copy out.
        float* stage = (float*)smem + wid * 256;   // 16 warps x 1KB = 16KB
        #pragma unroll
        for (int m = 0; m < 2; m++)
            #pragma unroll
            for (int n = 0; n < 4; n++) {
                wmma::store_matrix_sync(stage, acc[m][n], 16, wmma::mem_row_major);
                __syncwarp();
                const int r = lane >> 1;
                const int cc = (lane & 1) * 8;
                const int grow = rowBase + warp_m * 32 + m * 16 + r;
                const int col  = warp_n * 64 + n * 16 + cc;
                if (grow < N_NODES) {
                    float* p = (col < 128)
                             ? g_H + (size_t)grow * D_OUT + col
                             : out + (size_t)grow * D_OUT + (col - 128);
                    *(float4*)(p + 0) = *(float4*)(stage + r * 16 + cc + 0);
                    *(float4*)(p + 4) = *(float4*)(stage + r * 16 + cc + 4);
                }
                __syncwarp();
            }
    }
}

// ---------------------------------------------------------------------------
// Aggregate: one warp per dst node (grid-stride). Atomic-free, 4-edge unroll.
//   out[d] += bias + ( sum_e H[src_e] + (sum_e Xe_e) @ We ) / deg[d]
// ---------------------------------------------------------------------------
__global__ __launch_bounds__(256)
void aggregate_kernel(const float* __restrict__ Xe,
                      const float* __restrict__ We,    // [16][128]
                      const float* __restrict__ bias,
                      float* __restrict__ out) {
    const int lane = threadIdx.x & 31;
    const int col  = lane * 4;

    float4 w[D_EDGE];
    #pragma unroll
    for (int k = 0; k < D_EDGE; k++)
        w[k] = *(const float4*)(We + k * D_OUT + col);
    const float4 b = *(const float4*)(bias + col);

    const int warpId = (blockIdx.x * blockDim.x + threadIdx.x) >> 5;
    const int nWarps = (gridDim.x * blockDim.x) >> 5;

    for (int d = warpId; d < N_NODES; d += nWarps) {
        const int start = g_off[d];
        const int c     = g_deg[d];

        float4 h = make_float4(0.f, 0.f, 0.f, 0.f);
        float xacc0 = 0.f, xacc1 = 0.f;

        int i = 0;
        for (; i + 4 <= c; i += 4) {
            const unsigned long long pe0 = g_list[start + i + 0];
            const unsigned long long pe1 = g_list[start + i + 1];
            const unsigned long long pe2 = g_list[start + i + 2];
            const unsigned long long pe3 = g_list[start + i + 3];
            const int s0 = (int)(pe0 & 0xFFFFFFFFu), e0 = (int)(pe0 >> 32);
            const int s1 = (int)(pe1 & 0xFFFFFFFFu), e1 = (int)(pe1 >> 32);
            const int s2 = (int)(pe2 & 0xFFFFFFFFu), e2 = (int)(pe2 >> 32);
            const int s3 = (int)(pe3 & 0xFFFFFFFFu), e3 = (int)(pe3 >> 32);

            const float4 h0 = *(const float4*)(g_H + (size_t)s0 * D_OUT + col);
            const float4 h1 = *(const float4*)(g_H + (size_t)s1 * D_OUT + col);
            const float4 h2 = *(const float4*)(g_H + (size_t)s2 * D_OUT + col);
            const float4 h3 = *(const float4*)(g_H + (size_t)s3 * D_OUT + col);
            const float xv0 = (lane < 16) ? Xe[(size_t)e0 * D_EDGE + lane]
                                          : Xe[(size_t)e1 * D_EDGE + (lane - 16)];
            const float xv1 = (lane < 16) ? Xe[(size_t)e2 * D_EDGE + lane]
                                          : Xe[(size_t)e3 * D_EDGE + (lane - 16)];
            h.x += (h0.x + h1.x) + (h2.x + h3.x);
            h.y += (h0.y + h1.y) + (h2.y + h3.y);
            h.z += (h0.z + h1.z) + (h2.z + h3.z);
            h.w += (h0.w + h1.w) + (h2.w + h3.w);
            xacc0 += xv0;
            xacc1 += xv1;
        }
        for (; i < c; ++i) {
            const unsigned long long pe = g_list[start + i];
            const int s = (int)(pe & 0xFFFFFFFFu);
            const int e = (int)(pe >> 32);
            const float4 hv = *(const float4*)(g_H + (size_t)s * D_OUT + col);
            h.x += hv.x; h.y += hv.y; h.z += hv.z; h.w += hv.w;
            if (lane < 16) xacc0 += Xe[(size_t)e * D_EDGE + lane];
        }

        float4 o = *(const float4*)(out + (size_t)d * D_OUT + col);
        o.x += b.x; o.y += b.y; o.z += b.z; o.w += b.w;

        if (c > 0) {
            float4 p = make_float4(0.f, 0.f, 0.f, 0.f);
            #pragma unroll
            for (int k = 0; k < D_EDGE; k++) {
                const float xk = (__shfl_sync(0xFFFFFFFFu, xacc0, k) +
                                  __shfl_sync(0xFFFFFFFFu, xacc0, k + 16)) +
                                 (__shfl_sync(0xFFFFFFFFu, xacc1, k) +
                                  __shfl_sync(0xFFFFFFFFu, xacc1, k + 16));
                p.x = fmaf(xk, w[k].x, p.x);
                p.y = fmaf(xk, w[k].y, p.y);
                p.z = fmaf(xk, w[k].z, p.z);
                p.w = fmaf(xk, w[k].w, p.w);
            }
            const float inv = 1.0f / (float)c;
            o.x = fmaf(h.x + p.x, inv, o.x);
            o.y = fmaf(h.y + p.y, inv, o.y);
            o.z = fmaf(h.z + p.z, inv, o.z);
            o.w = fmaf(h.w + p.w, inv, o.w);
        }
        *(float4*)(out + (size_t)d * D_OUT + col) = o;
    }
}

// ---------------------------------------------------------------------------
// Launch
// ---------------------------------------------------------------------------
extern "C" void kernel_launch(void* const* d_in, const int* in_sizes, int n_in,
                              void* d_out, int out_size) {
    const float* X    = (const float*)d_in[0];
    const float* Xe   = (const float*)d_in[1];
    const float* Wn   = (const float*)d_in[2];
    const float* Ws   = (const float*)d_in[3];
    const float* bias = (const float*)d_in[4];
    const float* We   = (const float*)d_in[5];
    const int*   src  = (const int*)d_in[6];
    const int*   dst  = (const int*)d_in[7];
    float*       out  = (float*)d_out;

    cudaFuncSetAttribute(gemm_fused_kernel,
                         cudaFuncAttributeMaxDynamicSharedMemorySize, GEMM_SMEM);

    // CSR build
    zero_deg_kernel<<<(N_NODES + 255) / 256, 256>>>();
    hist_kernel<<<(N_EDGES + 255) / 256, 256>>>(dst);
    scanA_kernel<<<SCAN_NB, SCAN_BLK>>>();
    scanB_kernel<<<1, 128>>>();
    scanC_kernel<<<SCAN_NB, SCAN_BLK>>>();
    scatter_kernel<<<(N_EDGES + 255) / 256, 256>>>(src, dst);

    // Fused node GEMM: g_H = X@Wn ; out = X@Ws
    {
        const int grid = (N_NODES + TILE_M - 1) / TILE_M;   // 782
        gemm_fused_kernel<<<grid, 512, GEMM_SMEM>>>(X, Wn, Ws, out);
    }

    // Gather aggregation (fuses mean, edge projection, bias, final combine)
    aggregate_kernel<<<2048, 256>>>(Xe, We, bias, out);
}

// round 6
// speedup vs baseline: 2.9798x; 1.0603x over previous
#include <cuda_runtime.h>
#include <cuda_bf16.h>
#include <mma.h>
#include <cstdint>

using namespace nvcuda;

#define N_NODES 100000
#define N_EDGES 1600000
#define D_IN    256
#define D_EDGE  16
#define D_OUT   128

#define SCAN_BLK  1024
#define SCAN_NB   ((N_NODES + SCAN_BLK - 1) / SCAN_BLK)   // 98

// Scratch (allocation-free rule: __device__ globals)
__device__ float              g_H[(size_t)N_NODES * D_OUT];   // X @ W_neigh
__device__ int                g_deg[N_NODES + 1];             // in-degree; [N_NODES] = scan base counter
__device__ int                g_off[N_NODES];                 // CSR offsets
__device__ int                g_cursor[N_NODES];              // scatter cursors
__device__ unsigned long long g_list[N_EDGES];                // packed (edge<<32 | src)

__device__ __forceinline__ uint32_t pack_bf16(__nv_bfloat16 a, __nv_bfloat16 b) {
    __nv_bfloat162 t(a, b);
    return *reinterpret_cast<uint32_t*>(&t);
}
__device__ __forceinline__ void split_bf16(float x, __nv_bfloat16& hi, __nv_bfloat16& lo) {
    hi = __float2bfloat16(x);
    lo = __float2bfloat16(x - __bfloat162float(hi));
}

// ---------------------------------------------------------------------------
// CSR: histogram
// ---------------------------------------------------------------------------
__global__ void hist_kernel(const int* __restrict__ dst) {
    int e = blockIdx.x * blockDim.x + threadIdx.x;
    if (e < N_EDGES) atomicAdd(&g_deg[dst[e]], 1);
}

// ---------------------------------------------------------------------------
// CSR: one-shot scan. Block-local Hillis-Steele + atomic base grab.
// Bucket placement across blocks is non-deterministic but each node gets a
// private contiguous region, so the final output is invariant.
// ---------------------------------------------------------------------------
__global__ __launch_bounds__(SCAN_BLK)
void scan_kernel() {
    __shared__ int s[SCAN_BLK];
    __shared__ int base;
    const int t = threadIdx.x;
    const int i = blockIdx.x * SCAN_BLK + t;
    const int d = (i < N_NODES) ? g_deg[i] : 0;
    s[t] = d;
    __syncthreads();
    #pragma unroll
    for (int off = 1; off < SCAN_BLK; off <<= 1) {
        int v = (t >= off) ? s[t - off] : 0;
        __syncthreads();
        s[t] += v;
        __syncthreads();
    }
    if (t == SCAN_BLK - 1) base = atomicAdd(&g_deg[N_NODES], s[t]);
    __syncthreads();
    if (i < N_NODES) {
        const int o = base + s[t] - d;
        g_off[i] = o;
        g_cursor[i] = o;
    }
}

// ---------------------------------------------------------------------------
// Fused launch: blocks [0, GEMM_BLOCKS) run the wmma node GEMM,
// blocks [GEMM_BLOCKS, +SCAT_BLOCKS) run the CSR scatter (independent work).
// ---------------------------------------------------------------------------
#define TILE_M 128
#define KC     32
#define NCHUNK (D_IN / KC)   // 8
#define LDA    40            // As row stride (bf16), 80B
#define LDB    264           // Bs row stride (bf16), 528B
#define OFF_AS_HI 0
#define OFF_AS_LO 10240
#define OFF_BS_HI 20480
#define OFF_BS_LO 37376
#define GEMM_SMEM 54272

#define GEMM_BLOCKS ((N_NODES + TILE_M - 1) / TILE_M)        // 782
#define SCAT_BLOCKS ((N_EDGES + 511) / 512)                  // 3125

__global__ __launch_bounds__(512)
void gemm_scatter_kernel(const float* __restrict__ X,
                         const float* __restrict__ Wn,
                         const float* __restrict__ Ws,
                         float* __restrict__ out,
                         const int* __restrict__ src,
                         const int* __restrict__ dst) {
    // ---------------- scatter partition ----------------
    if (blockIdx.x >= GEMM_BLOCKS) {
        const int e = (blockIdx.x - GEMM_BLOCKS) * 512 + threadIdx.x;
        if (e < N_EDGES) {
            const int d = dst[e];
            const int pos = atomicAdd(&g_cursor[d], 1);
            g_list[pos] = ((unsigned long long)(unsigned)e << 32) | (unsigned)src[e];
        }
        return;
    }

    // ---------------- GEMM partition ----------------
    extern __shared__ char smem[];
    __nv_bfloat16* As_hi = (__nv_bfloat16*)(smem + OFF_AS_HI);
    __nv_bfloat16* As_lo = (__nv_bfloat16*)(smem + OFF_AS_LO);
    __nv_bfloat16* Bs_hi = (__nv_bfloat16*)(smem + OFF_BS_HI);
    __nv_bfloat16* Bs_lo = (__nv_bfloat16*)(smem + OFF_BS_LO);

    const int tid  = threadIdx.x;
    const int wid  = tid >> 5;
    const int lane = tid & 31;
    const int warp_m = wid & 3;      // 4 warps in M (32 rows each)
    const int warp_n = wid >> 2;     // 4 warps in N (64 cols each)
    const int rowBase = blockIdx.x * TILE_M;

    // A loader: 128 rows x 32 cols, 8 floats per thread
    const int arow  = tid >> 2;
    const int acol  = (tid & 3) * 8;
    const int agrow = rowBase + arow;
    // B loader: 32 rows x 256 cols, 16 floats per thread
    const int brow = tid >> 4;
    const int bcol = (tid & 15) * 16;
    const float* __restrict__ Wsel = (bcol < 128) ? Wn : Ws;
    const int wcol = bcol & 127;

    wmma::fragment<wmma::accumulator, 16, 16, 16, float> acc[2][4];
    #pragma unroll
    for (int m = 0; m < 2; m++)
        #pragma unroll
        for (int n = 0; n < 4; n++)
            wmma::fill_fragment(acc[m][n], 0.0f);

    float4 pa[2], pb[4];
    #pragma unroll
    for (int j = 0; j < 2; j++)
        pa[j] = (agrow < N_NODES)
              ? *(const float4*)(X + (size_t)agrow * D_IN + acol + j * 4)
              : make_float4(0.f, 0.f, 0.f, 0.f);
    #pragma unroll
    for (int j = 0; j < 4; j++)
        pb[j] = *(const float4*)(Wsel + (size_t)brow * D_OUT + wcol + j * 4);

    for (int c = 0; c < NCHUNK; ++c) {
        #pragma unroll
        for (int j = 0; j < 2; j++) {
            __nv_bfloat16 h0,h1,h2,h3,l0,l1,l2,l3;
            split_bf16(pa[j].x, h0, l0); split_bf16(pa[j].y, h1, l1);
            split_bf16(pa[j].z, h2, l2); split_bf16(pa[j].w, h3, l3);
            const int o = arow * LDA + acol + j * 4;
            *(uint2*)(As_hi + o) = make_uint2(pack_bf16(h0,h1), pack_bf16(h2,h3));
            *(uint2*)(As_lo + o) = make_uint2(pack_bf16(l0,l1), pack_bf16(l2,l3));
        }
        #pragma unroll
        for (int j = 0; j < 4; j++) {
            __nv_bfloat16 h0,h1,h2,h3,l0,l1,l2,l3;
            split_bf16(pb[j].x, h0, l0); split_bf16(pb[j].y, h1, l1);
            split_bf16(pb[j].z, h2, l2); split_bf16(pb[j].w, h3, l3);
            const int o = brow * LDB + bcol + j * 4;
            *(uint2*)(Bs_hi + o) = make_uint2(pack_bf16(h0,h1), pack_bf16(h2,h3));
            *(uint2*)(Bs_lo + o) = make_uint2(pack_bf16(l0,l1), pack_bf16(l2,l3));
        }
        __syncthreads();

        if (c + 1 < NCHUNK) {
            const int k0 = (c + 1) * KC;
            #pragma unroll
            for (int j = 0; j < 2; j++)
                pa[j] = (agrow < N_NODES)
                      ? *(const float4*)(X + (size_t)agrow * D_IN + k0 + acol + j * 4)
                      : make_float4(0.f, 0.f, 0.f, 0.f);
            #pragma unroll
            for (int j = 0; j < 4; j++)
                pb[j] = *(const float4*)(Wsel + (size_t)(k0 + brow) * D_OUT + wcol + j * 4);
        }

        #pragma unroll
        for (int ks = 0; ks < KC / 16; ks++) {
            wmma::fragment<wmma::matrix_a, 16, 16, 16, __nv_bfloat16, wmma::row_major> a_hi[2], a_lo[2];
            #pragma unroll
            for (int m = 0; m < 2; m++) {
                wmma::load_matrix_sync(a_hi[m], As_hi + (warp_m * 32 + m * 16) * LDA + ks * 16, LDA);
                wmma::load_matrix_sync(a_lo[m], As_lo + (warp_m * 32 + m * 16) * LDA + ks * 16, LDA);
            }
            #pragma unroll
            for (int n = 0; n < 4; n++) {
                wmma::fragment<wmma::matrix_b, 16, 16, 16, __nv_bfloat16, wmma::row_major> b_hi, b_lo;
                wmma::load_matrix_sync(b_hi, Bs_hi + (ks * 16) * LDB + warp_n * 64 + n * 16, LDB);
                wmma::load_matrix_sync(b_lo, Bs_lo + (ks * 16) * LDB + warp_n * 64 + n * 16, LDB);
                #pragma unroll
                for (int m = 0; m < 2; m++) {
                    wmma::mma_sync(acc[m][n], a_hi[m], b_hi, acc[m][n]);
                    wmma::mma_sync(acc[m][n], a_hi[m], b_lo, acc[m][n]);
                    wmma::mma_sync(acc[m][n], a_lo[m], b_hi, acc[m][n]);
                }
            }
        }
        __syncthreads();
    }

    if (rowBase + TILE_M <= N_NODES) {
        #pragma unroll
        for (int m = 0; m < 2; m++)
            #pragma unroll
            for (int n = 0; n < 4; n++) {
                const int row  = rowBase + warp_m * 32 + m * 16;
                const int col  = warp_n * 64 + n * 16;
                float* p = (col < 128)
                         ? g_H + (size_t)row * D_OUT + col
                         : out + (size_t)row * D_OUT + (col - 128);
                wmma::store_matrix_sync(p, acc[m][n], D_OUT, wmma::mem_row_major);
            }
    } else {
        float* stage = (float*)smem + wid * 256;
        #pragma unroll
        for (int m = 0; m < 2; m++)
            #pragma unroll
            for (int n = 0; n < 4; n++) {
                wmma::store_matrix_sync(stage, acc[m][n], 16, wmma::mem_row_major);
                __syncwarp();
                const int r = lane >> 1;
                const int cc = (lane & 1) * 8;
                const int grow = rowBase + warp_m * 32 + m * 16 + r;
                const int col  = warp_n * 64 + n * 16 + cc;
                if (grow < N_NODES) {
                    float* p = (col < 128)
                             ? g_H + (size_t)grow * D_OUT + col
                             : out + (size_t)grow * D_OUT + (col - 128);
                    *(float4*)(p + 0) = *(float4*)(stage + r * 16 + cc + 0);
                    *(float4*)(p + 4) = *(float4*)(stage + r * 16 + cc + 4);
                }
                __syncwarp();
            }
    }
}

// ---------------------------------------------------------------------------
// Aggregate: one warp per dst node (grid-stride). Atomic-free, 4-edge unroll.
//   out[d] += bias + ( sum_e H[src_e] + (sum_e Xe_e) @ We ) / deg[d]
// ---------------------------------------------------------------------------
__global__ __launch_bounds__(256)
void aggregate_kernel(const float* __restrict__ Xe,
                      const float* __restrict__ We,    // [16][128]
                      const float* __restrict__ bias,
                      float* __restrict__ out) {
    const int lane = threadIdx.x & 31;
    const int col  = lane * 4;

    float4 w[D_EDGE];
    #pragma unroll
    for (int k = 0; k < D_EDGE; k++)
        w[k] = *(const float4*)(We + k * D_OUT + col);
    const float4 b = *(const float4*)(bias + col);

    const int warpId = (blockIdx.x * blockDim.x + threadIdx.x) >> 5;
    const int nWarps = (gridDim.x * blockDim.x) >> 5;

    for (int d = warpId; d < N_NODES; d += nWarps) {
        const int start = g_off[d];
        const int c     = g_deg[d];

        // Independent early load (overlaps with the gather loop)
        float4 o = *(const float4*)(out + (size_t)d * D_OUT + col);

        float4 h = make_float4(0.f, 0.f, 0.f, 0.f);
        float xacc0 = 0.f, xacc1 = 0.f;

        int i = 0;
        for (; i + 4 <= c; i += 4) {
            const unsigned long long pe0 = g_list[start + i + 0];
            const unsigned long long pe1 = g_list[start + i + 1];
            const unsigned long long pe2 = g_list[start + i + 2];
            const unsigned long long pe3 = g_list[start + i + 3];
            const int s0 = (int)(pe0 & 0xFFFFFFFFu), e0 = (int)(pe0 >> 32);
            const int s1 = (int)(pe1 & 0xFFFFFFFFu), e1 = (int)(pe1 >> 32);
            const int s2 = (int)(pe2 & 0xFFFFFFFFu), e2 = (int)(pe2 >> 32);
            const int s3 = (int)(pe3 & 0xFFFFFFFFu), e3 = (int)(pe3 >> 32);

            const float4 h0 = *(const float4*)(g_H + (size_t)s0 * D_OUT + col);
            const float4 h1 = *(const float4*)(g_H + (size_t)s1 * D_OUT + col);
            const float4 h2 = *(const float4*)(g_H + (size_t)s2 * D_OUT + col);
            const float4 h3 = *(const float4*)(g_H + (size_t)s3 * D_OUT + col);
            const float xv0 = (lane < 16) ? Xe[(size_t)e0 * D_EDGE + lane]
                                          : Xe[(size_t)e1 * D_EDGE + (lane - 16)];
            const float xv1 = (lane < 16) ? Xe[(size_t)e2 * D_EDGE + lane]
                                          : Xe[(size_t)e3 * D_EDGE + (lane - 16)];
            h.x += (h0.x + h1.x) + (h2.x + h3.x);
            h.y += (h0.y + h1.y) + (h2.y + h3.y);
            h.z += (h0.z + h1.z) + (h2.z + h3.z);
            h.w += (h0.w + h1.w) + (h2.w + h3.w);
            xacc0 += xv0;
            xacc1 += xv1;
        }
        for (; i < c; ++i) {
            const unsigned long long pe = g_list[start + i];
            const int s = (int)(pe & 0xFFFFFFFFu);
            const int e = (int)(pe >> 32);
            const float4 hv = *(const float4*)(g_H + (size_t)s * D_OUT + col);
            h.x += hv.x; h.y += hv.y; h.z += hv.z; h.w += hv.w;
            if (lane < 16) xacc0 += Xe[(size_t)e * D_EDGE + lane];
        }

        o.x += b.x; o.y += b.y; o.z += b.z; o.w += b.w;

        if (c > 0) {
            float4 p = make_float4(0.f, 0.f, 0.f, 0.f);
            #pragma unroll
            for (int k = 0; k < D_EDGE; k++) {
                const float xk = (__shfl_sync(0xFFFFFFFFu, xacc0, k) +
                                  __shfl_sync(0xFFFFFFFFu, xacc0, k + 16)) +
                                 (__shfl_sync(0xFFFFFFFFu, xacc1, k) +
                                  __shfl_sync(0xFFFFFFFFu, xacc1, k + 16));
                p.x = fmaf(xk, w[k].x, p.x);
                p.y = fmaf(xk, w[k].y, p.y);
                p.z = fmaf(xk, w[k].z, p.z);
                p.w = fmaf(xk, w[k].w, p.w);
            }
            const float inv = 1.0f / (float)c;
            o.x = fmaf(h.x + p.x, inv, o.x);
            o.y = fmaf(h.y + p.y, inv, o.y);
            o.z = fmaf(h.z + p.z, inv, o.z);
            o.w = fmaf(h.w + p.w, inv, o.w);
        }
        *(float4*)(out + (size_t)d * D_OUT + col) = o;
    }
}

// ---------------------------------------------------------------------------
// Launch
// ---------------------------------------------------------------------------
extern "C" void kernel_launch(void* const* d_in, const int* in_sizes, int n_in,
                              void* d_out, int out_size) {
    const float* X    = (const float*)d_in[0];
    const float* Xe   = (const float*)d_in[1];
    const float* Wn   = (const float*)d_in[2];
    const float* Ws   = (const float*)d_in[3];
    const float* bias = (const float*)d_in[4];
    const float* We   = (const float*)d_in[5];
    const int*   src  = (const int*)d_in[6];
    const int*   dst  = (const int*)d_in[7];
    float*       out  = (float*)d_out;

    cudaFuncSetAttribute(gemm_scatter_kernel,
                         cudaFuncAttributeMaxDynamicSharedMemorySize, GEMM_SMEM);

    // 1) zero degree array + scan-base counter (memset node, no kernel)
    void* degAddr = nullptr;
    cudaGetSymbolAddress(&degAddr, g_deg);
    cudaMemsetAsync(degAddr, 0, (N_NODES + 1) * sizeof(int));

    // 2) histogram of dst
    hist_kernel<<<(N_EDGES + 255) / 256, 256>>>(dst);

    // 3) one-shot scan (block scan + atomic base grab)
    scan_kernel<<<SCAN_NB, SCAN_BLK>>>();

    // 4) fused: node GEMM (g_H = X@Wn ; out = X@Ws) + CSR scatter
    gemm_scatter_kernel<<<GEMM_BLOCKS + SCAT_BLOCKS, 512, GEMM_SMEM>>>(
        X, Wn, Ws, out, src, dst);

    // 5) gather aggregation (fuses mean, edge projection, bias, final combine)
    aggregate_kernel<<<2048, 256>>>(Xe, We, bias, out);
}

// round 7
// speedup vs baseline: 3.2867x; 1.1030x over previous
#include <cuda_runtime.h>
#include <cuda_bf16.h>
#include <mma.h>
#include <cstdint>

using namespace nvcuda;

#define N_NODES 100000
#define N_EDGES 1600000
#define D_IN    256
#define D_EDGE  16
#define D_OUT   128

#define SCAN_BLK  1024
#define SCAN_NB   ((N_NODES + SCAN_BLK - 1) / SCAN_BLK)   // 98

// Scratch (allocation-free rule: __device__ globals)
__device__ float              g_H[(size_t)N_NODES * D_OUT];   // X @ W_neigh
__device__ int                g_deg[N_NODES + 1];             // in-degree; [N_NODES] = scan base counter
__device__ int                g_off[N_NODES];                 // CSR offsets
__device__ int                g_cursor[N_NODES];              // scatter cursors
__device__ unsigned long long g_list[N_EDGES];                // packed (edge<<32 | src)

__device__ __forceinline__ uint32_t pack_bf16(__nv_bfloat16 a, __nv_bfloat16 b) {
    __nv_bfloat162 t(a, b);
    return *reinterpret_cast<uint32_t*>(&t);
}
__device__ __forceinline__ void split_bf16(float x, __nv_bfloat16& hi, __nv_bfloat16& lo) {
    hi = __float2bfloat16(x);
    lo = __float2bfloat16(x - __bfloat162float(hi));
}

// ---------------------------------------------------------------------------
// CSR: histogram (int4 loads, 4 edges per thread)
// ---------------------------------------------------------------------------
__global__ void hist_kernel(const int* __restrict__ dst) {
    int i = blockIdx.x * blockDim.x + threadIdx.x;
    if (i * 4 + 3 < N_EDGES) {
        const int4 d4 = *(const int4*)(dst + i * 4);
        atomicAdd(&g_deg[d4.x], 1);
        atomicAdd(&g_deg[d4.y], 1);
        atomicAdd(&g_deg[d4.z], 1);
        atomicAdd(&g_deg[d4.w], 1);
    } else {
        for (int e = i * 4; e < N_EDGES; ++e)
            atomicAdd(&g_deg[dst[e]], 1);
    }
}

// ---------------------------------------------------------------------------
// CSR: one-shot scan. Block-local Hillis-Steele + atomic base grab.
// ---------------------------------------------------------------------------
__global__ __launch_bounds__(SCAN_BLK)
void scan_kernel() {
    __shared__ int s[SCAN_BLK];
    __shared__ int base;
    const int t = threadIdx.x;
    const int i = blockIdx.x * SCAN_BLK + t;
    const int d = (i < N_NODES) ? g_deg[i] : 0;
    s[t] = d;
    __syncthreads();
    #pragma unroll
    for (int off = 1; off < SCAN_BLK; off <<= 1) {
        int v = (t >= off) ? s[t - off] : 0;
        __syncthreads();
        s[t] += v;
        __syncthreads();
    }
    if (t == SCAN_BLK - 1) base = atomicAdd(&g_deg[N_NODES], s[t]);
    __syncthreads();
    if (i < N_NODES) {
        const int o = base + s[t] - d;
        g_off[i] = o;
        g_cursor[i] = o;
    }
}

// ---------------------------------------------------------------------------
// Fused launch: blocks [0, GEMM_BLOCKS) run the wmma node GEMM,
// blocks [GEMM_BLOCKS, +SCAT_BLOCKS) run the CSR scatter (independent work).
// ---------------------------------------------------------------------------
#define TILE_M 128
#define KC     32
#define NCHUNK (D_IN / KC)   // 8
#define LDA    40            // As row stride (bf16), 80B
#define LDB    264           // Bs row stride (bf16), 528B
#define OFF_AS_HI 0
#define OFF_AS_LO 10240
#define OFF_BS_HI 20480
#define OFF_BS_LO 37376
#define GEMM_SMEM 54272

#define GEMM_BLOCKS ((N_NODES + TILE_M - 1) / TILE_M)        // 782
#define SCAT_BLOCKS ((N_EDGES + 511) / 512)                  // 3125

__global__ __launch_bounds__(512)
void gemm_scatter_kernel(const float* __restrict__ X,
                         const float* __restrict__ Wn,
                         const float* __restrict__ Ws,
                         float* __restrict__ out,
                         const int* __restrict__ src,
                         const int* __restrict__ dst) {
    // ---------------- scatter partition ----------------
    if (blockIdx.x >= GEMM_BLOCKS) {
        const int e = (blockIdx.x - GEMM_BLOCKS) * 512 + threadIdx.x;
        if (e < N_EDGES) {
            const int d = dst[e];
            const int pos = atomicAdd(&g_cursor[d], 1);
            g_list[pos] = ((unsigned long long)(unsigned)e << 32) | (unsigned)src[e];
        }
        return;
    }

    // ---------------- GEMM partition ----------------
    extern __shared__ char smem[];
    __nv_bfloat16* As_hi = (__nv_bfloat16*)(smem + OFF_AS_HI);
    __nv_bfloat16* As_lo = (__nv_bfloat16*)(smem + OFF_AS_LO);
    __nv_bfloat16* Bs_hi = (__nv_bfloat16*)(smem + OFF_BS_HI);
    __nv_bfloat16* Bs_lo = (__nv_bfloat16*)(smem + OFF_BS_LO);

    const int tid  = threadIdx.x;
    const int wid  = tid >> 5;
    const int lane = tid & 31;
    const int warp_m = wid & 3;
    const int warp_n = wid >> 2;
    const int rowBase = blockIdx.x * TILE_M;

    const int arow  = tid >> 2;
    const int acol  = (tid & 3) * 8;
    const int agrow = rowBase + arow;
    const int brow = tid >> 4;
    const int bcol = (tid & 15) * 16;
    const float* __restrict__ Wsel = (bcol < 128) ? Wn : Ws;
    const int wcol = bcol & 127;

    wmma::fragment<wmma::accumulator, 16, 16, 16, float> acc[2][4];
    #pragma unroll
    for (int m = 0; m < 2; m++)
        #pragma unroll
        for (int n = 0; n < 4; n++)
            wmma::fill_fragment(acc[m][n], 0.0f);

    float4 pa[2], pb[4];
    #pragma unroll
    for (int j = 0; j < 2; j++)
        pa[j] = (agrow < N_NODES)
              ? *(const float4*)(X + (size_t)agrow * D_IN + acol + j * 4)
              : make_float4(0.f, 0.f, 0.f, 0.f);
    #pragma unroll
    for (int j = 0; j < 4; j++)
        pb[j] = *(const float4*)(Wsel + (size_t)brow * D_OUT + wcol + j * 4);

    for (int c = 0; c < NCHUNK; ++c) {
        #pragma unroll
        for (int j = 0; j < 2; j++) {
            __nv_bfloat16 h0,h1,h2,h3,l0,l1,l2,l3;
            split_bf16(pa[j].x, h0, l0); split_bf16(pa[j].y, h1, l1);
            split_bf16(pa[j].z, h2, l2); split_bf16(pa[j].w, h3, l3);
            const int o = arow * LDA + acol + j * 4;
            *(uint2*)(As_hi + o) = make_uint2(pack_bf16(h0,h1), pack_bf16(h2,h3));
            *(uint2*)(As_lo + o) = make_uint2(pack_bf16(l0,l1), pack_bf16(l2,l3));
        }
        #pragma unroll
        for (int j = 0; j < 4; j++) {
            __nv_bfloat16 h0,h1,h2,h3,l0,l1,l2,l3;
            split_bf16(pb[j].x, h0, l0); split_bf16(pb[j].y, h1, l1);
            split_bf16(pb[j].z, h2, l2); split_bf16(pb[j].w, h3, l3);
            const int o = brow * LDB + bcol + j * 4;
            *(uint2*)(Bs_hi + o) = make_uint2(pack_bf16(h0,h1), pack_bf16(h2,h3));
            *(uint2*)(Bs_lo + o) = make_uint2(pack_bf16(l0,l1), pack_bf16(l2,l3));
        }
        __syncthreads();

        if (c + 1 < NCHUNK) {
            const int k0 = (c + 1) * KC;
            #pragma unroll
            for (int j = 0; j < 2; j++)
                pa[j] = (agrow < N_NODES)
                      ? *(const float4*)(X + (size_t)agrow * D_IN + k0 + acol + j * 4)
                      : make_float4(0.f, 0.f, 0.f, 0.f);
            #pragma unroll
            for (int j = 0; j < 4; j++)
                pb[j] = *(const float4*)(Wsel + (size_t)(k0 + brow) * D_OUT + wcol + j * 4);
        }

        #pragma unroll
        for (int ks = 0; ks < KC / 16; ks++) {
            wmma::fragment<wmma::matrix_a, 16, 16, 16, __nv_bfloat16, wmma::row_major> a_hi[2], a_lo[2];
            #pragma unroll
            for (int m = 0; m < 2; m++) {
                wmma::load_matrix_sync(a_hi[m], As_hi + (warp_m * 32 + m * 16) * LDA + ks * 16, LDA);
                wmma::load_matrix_sync(a_lo[m], As_lo + (warp_m * 32 + m * 16) * LDA + ks * 16, LDA);
            }
            #pragma unroll
            for (int n = 0; n < 4; n++) {
                wmma::fragment<wmma::matrix_b, 16, 16, 16, __nv_bfloat16, wmma::row_major> b_hi, b_lo;
                wmma::load_matrix_sync(b_hi, Bs_hi + (ks * 16) * LDB + warp_n * 64 + n * 16, LDB);
                wmma::load_matrix_sync(b_lo, Bs_lo + (ks * 16) * LDB + warp_n * 64 + n * 16, LDB);
                #pragma unroll
                for (int m = 0; m < 2; m++) {
                    wmma::mma_sync(acc[m][n], a_hi[m], b_hi, acc[m][n]);
                    wmma::mma_sync(acc[m][n], a_hi[m], b_lo, acc[m][n]);
                    wmma::mma_sync(acc[m][n], a_lo[m], b_hi, acc[m][n]);
                }
            }
        }
        __syncthreads();
    }

    if (rowBase + TILE_M <= N_NODES) {
        #pragma unroll
        for (int m = 0; m < 2; m++)
            #pragma unroll
            for (int n = 0; n < 4; n++) {
                const int row  = rowBase + warp_m * 32 + m * 16;
                const int col  = warp_n * 64 + n * 16;
                float* p = (col < 128)
                         ? g_H + (size_t)row * D_OUT + col
                         : out + (size_t)row * D_OUT + (col - 128);
                wmma::store_matrix_sync(p, acc[m][n], D_OUT, wmma::mem_row_major);
            }
    } else {
        float* stage = (float*)smem + wid * 256;
        #pragma unroll
        for (int m = 0; m < 2; m++)
            #pragma unroll
            for (int n = 0; n < 4; n++) {
                wmma::store_matrix_sync(stage, acc[m][n], 16, wmma::mem_row_major);
                __syncwarp();
                const int r = lane >> 1;
                const int cc = (lane & 1) * 8;
                const int grow = rowBase + warp_m * 32 + m * 16 + r;
                const int col  = warp_n * 64 + n * 16 + cc;
                if (grow < N_NODES) {
                    float* p = (col < 128)
                             ? g_H + (size_t)grow * D_OUT + col
                             : out + (size_t)grow * D_OUT + (col - 128);
                    *(float4*)(p + 0) = *(float4*)(stage + r * 16 + cc + 0);
                    *(float4*)(p + 4) = *(float4*)(stage + r * 16 + cc + 4);
                }
                __syncwarp();
            }
    }
}

// ---------------------------------------------------------------------------
// Aggregate: one warp per dst node (grid-stride). Atomic-free, 4-edge unroll.
// W_edge lives in SHARED memory (frees ~64 regs -> 2x occupancy).
//   out[d] += bias + ( sum_e H[src_e] + (sum_e Xe_e) @ We ) / deg[d]
// ---------------------------------------------------------------------------
__global__ __launch_bounds__(256, 4)
void aggregate_kernel(const float* __restrict__ Xe,
                      const float* __restrict__ We,    // [16][128]
                      const float* __restrict__ bias,
                      float* __restrict__ out) {
    __shared__ float4 sW[D_EDGE][32];   // [k][lane] = We[k][lane*4 .. +3], 8KB

    const int tid  = threadIdx.x;
    const int lane = tid & 31;
    const int col  = lane * 4;

    // Cooperative one-time load of W_edge into smem
    for (int i = tid; i < D_EDGE * 32; i += 256) {
        const int k = i >> 5, l = i & 31;
        sW[k][l] = *(const float4*)(We + k * D_OUT + l * 4);
    }
    __syncthreads();

    const float4 b = *(const float4*)(bias + col);

    const int warpId = (blockIdx.x * blockDim.x + tid) >> 5;
    const int nWarps = (gridDim.x * blockDim.x) >> 5;

    for (int d = warpId; d < N_NODES; d += nWarps) {
        const int start = g_off[d];
        const int c     = g_deg[d];

        // Independent early load (overlaps with the gather loop)
        float4 o = *(const float4*)(out + (size_t)d * D_OUT + col);

        float4 h = make_float4(0.f, 0.f, 0.f, 0.f);
        float xacc0 = 0.f, xacc1 = 0.f;

        int i = 0;
        for (; i + 4 <= c; i += 4) {
            const unsigned long long pe0 = g_list[start + i + 0];
            const unsigned long long pe1 = g_list[start + i + 1];
            const unsigned long long pe2 = g_list[start + i + 2];
            const unsigned long long pe3 = g_list[start + i + 3];
            const int s0 = (int)(pe0 & 0xFFFFFFFFu), e0 = (int)(pe0 >> 32);
            const int s1 = (int)(pe1 & 0xFFFFFFFFu), e1 = (int)(pe1 >> 32);
            const int s2 = (int)(pe2 & 0xFFFFFFFFu), e2 = (int)(pe2 >> 32);
            const int s3 = (int)(pe3 & 0xFFFFFFFFu), e3 = (int)(pe3 >> 32);

            const float4 h0 = *(const float4*)(g_H + (size_t)s0 * D_OUT + col);
            const float4 h1 = *(const float4*)(g_H + (size_t)s1 * D_OUT + col);
            const float4 h2 = *(const float4*)(g_H + (size_t)s2 * D_OUT + col);
            const float4 h3 = *(const float4*)(g_H + (size_t)s3 * D_OUT + col);
            const float xv0 = (lane < 16) ? Xe[(size_t)e0 * D_EDGE + lane]
                                          : Xe[(size_t)e1 * D_EDGE + (lane - 16)];
            const float xv1 = (lane < 16) ? Xe[(size_t)e2 * D_EDGE + lane]
                                          : Xe[(size_t)e3 * D_EDGE + (lane - 16)];
            h.x += (h0.x + h1.x) + (h2.x + h3.x);
            h.y += (h0.y + h1.y) + (h2.y + h3.y);
            h.z += (h0.z + h1.z) + (h2.z + h3.z);
            h.w += (h0.w + h1.w) + (h2.w + h3.w);
            xacc0 += xv0;
            xacc1 += xv1;
        }
        for (; i < c; ++i) {
            const unsigned long long pe = g_list[start + i];
            const int s = (int)(pe & 0xFFFFFFFFu);
            const int e = (int)(pe >> 32);
            const float4 hv = *(const float4*)(g_H + (size_t)s * D_OUT + col);
            h.x += hv.x; h.y += hv.y; h.z += hv.z; h.w += hv.w;
            if (lane < 16) xacc0 += Xe[(size_t)e * D_EDGE + lane];
        }

        o.x += b.x; o.y += b.y; o.z += b.z; o.w += b.w;

        if (c > 0) {
            float4 p = make_float4(0.f, 0.f, 0.f, 0.f);
            #pragma unroll
            for (int k = 0; k < D_EDGE; k++) {
                const float xk = (__shfl_sync(0xFFFFFFFFu, xacc0, k) +
                                  __shfl_sync(0xFFFFFFFFu, xacc0, k + 16)) +
                                 (__shfl_sync(0xFFFFFFFFu, xacc1, k) +
                                  __shfl_sync(0xFFFFFFFFu, xacc1, k + 16));
                const float4 wk = sW[k][lane];
                p.x = fmaf(xk, wk.x, p.x);
                p.y = fmaf(xk, wk.y, p.y);
                p.z = fmaf(xk, wk.z, p.z);
                p.w = fmaf(xk, wk.w, p.w);
            }
            const float inv = 1.0f / (float)c;
            o.x = fmaf(h.x + p.x, inv, o.x);
            o.y = fmaf(h.y + p.y, inv, o.y);
            o.z = fmaf(h.z + p.z, inv, o.z);
            o.w = fmaf(h.w + p.w, inv, o.w);
        }
        *(float4*)(out + (size_t)d * D_OUT + col) = o;
    }
}

// ---------------------------------------------------------------------------
// Launch
// ---------------------------------------------------------------------------
extern "C" void kernel_launch(void* const* d_in, const int* in_sizes, int n_in,
                              void* d_out, int out_size) {
    const float* X    = (const float*)d_in[0];
    const float* Xe   = (const float*)d_in[1];
    const float* Wn   = (const float*)d_in[2];
    const float* Ws   = (const float*)d_in[3];
    const float* bias = (const float*)d_in[4];
    const float* We   = (const float*)d_in[5];
    const int*   src  = (const int*)d_in[6];
    const int*   dst  = (const int*)d_in[7];
    float*       out  = (float*)d_out;

    cudaFuncSetAttribute(gemm_scatter_kernel,
                         cudaFuncAttributeMaxDynamicSharedMemorySize, GEMM_SMEM);

    // 1) zero degree array + scan-base counter (memset node, no kernel)
    void* degAddr = nullptr;
    cudaGetSymbolAddress(&degAddr, g_deg);
    cudaMemsetAsync(degAddr, 0, (N_NODES + 1) * sizeof(int));

    // 2) histogram of dst (4 edges per thread)
    hist_kernel<<<(N_EDGES / 4 + 255) / 256, 256>>>(dst);

    // 3) one-shot scan (block scan + atomic base grab)
    scan_kernel<<<SCAN_NB, SCAN_BLK>>>();

    // 4) fused: node GEMM (g_H = X@Wn ; out = X@Ws) + CSR scatter
    gemm_scatter_kernel<<<GEMM_BLOCKS + SCAT_BLOCKS, 512, GEMM_SMEM>>>(
        X, Wn, Ws, out, src, dst);

    // 5) gather aggregation (fuses mean, edge projection, bias, final combine)
    aggregate_kernel<<<2048, 256>>>(Xe, We, bias, out);
}

// round 8
// speedup vs baseline: 3.5342x; 1.0753x over previous
#include <cuda_runtime.h>
#include <cuda_bf16.h>
#include <mma.h>
#include <cstdint>

using namespace nvcuda;

#define N_NODES 100000
#define N_EDGES 1600000
#define D_IN    256
#define D_EDGE  16
#define D_OUT   128

#define SCAN_BLK  1024
#define SCAN_NB   ((N_NODES + SCAN_BLK - 1) / SCAN_BLK)   // 98

// Scratch (allocation-free rule: __device__ globals)
__device__ __nv_bfloat16      g_Hb[(size_t)N_NODES * D_OUT]; // X @ W_neigh (bf16)
__device__ int                g_deg[N_NODES + 1];            // in-degree; [N_NODES] = scan base
__device__ int                g_off[N_NODES];                // CSR offsets
__device__ int                g_cursor[N_NODES];             // scatter cursors
__device__ unsigned long long g_list[N_EDGES];               // packed (edge<<32 | src)

__device__ __forceinline__ uint32_t pack_bf16(__nv_bfloat16 a, __nv_bfloat16 b) {
    __nv_bfloat162 t(a, b);
    return *reinterpret_cast<uint32_t*>(&t);
}
__device__ __forceinline__ void split_bf16(float x, __nv_bfloat16& hi, __nv_bfloat16& lo) {
    hi = __float2bfloat16(x);
    lo = __float2bfloat16(x - __bfloat162float(hi));
}

// ---------------------------------------------------------------------------
// CSR: histogram (int4 loads, 4 edges per thread)
// ---------------------------------------------------------------------------
__global__ void hist_kernel(const int* __restrict__ dst) {
    int i = blockIdx.x * blockDim.x + threadIdx.x;
    if (i * 4 + 3 < N_EDGES) {
        const int4 d4 = *(const int4*)(dst + i * 4);
        atomicAdd(&g_deg[d4.x], 1);
        atomicAdd(&g_deg[d4.y], 1);
        atomicAdd(&g_deg[d4.z], 1);
        atomicAdd(&g_deg[d4.w], 1);
    } else {
        for (int e = i * 4; e < N_EDGES; ++e)
            atomicAdd(&g_deg[dst[e]], 1);
    }
}

// ---------------------------------------------------------------------------
// CSR: one-shot scan. Block-local Hillis-Steele + atomic base grab.
// ---------------------------------------------------------------------------
__global__ __launch_bounds__(SCAN_BLK)
void scan_kernel() {
    __shared__ int s[SCAN_BLK];
    __shared__ int base;
    const int t = threadIdx.x;
    const int i = blockIdx.x * SCAN_BLK + t;
    const int d = (i < N_NODES) ? g_deg[i] : 0;
    s[t] = d;
    __syncthreads();
    #pragma unroll
    for (int off = 1; off < SCAN_BLK; off <<= 1) {
        int v = (t >= off) ? s[t - off] : 0;
        __syncthreads();
        s[t] += v;
        __syncthreads();
    }
    if (t == SCAN_BLK - 1) base = atomicAdd(&g_deg[N_NODES], s[t]);
    __syncthreads();
    if (i < N_NODES) {
        const int o = base + s[t] - d;
        g_off[i] = o;
        g_cursor[i] = o;
    }
}

// ---------------------------------------------------------------------------
// Fused launch: blocks [0, GEMM_BLOCKS) run the wmma node GEMM,
// blocks [GEMM_BLOCKS, +SCAT_BLOCKS) run the CSR scatter (independent work).
// ---------------------------------------------------------------------------
#define TILE_M 128
#define KC     32
#define NCHUNK (D_IN / KC)   // 8
#define LDA    40            // As row stride (bf16), 80B
#define LDB    264           // Bs row stride (bf16), 528B
#define OFF_AS_HI 0
#define OFF_AS_LO 10240
#define OFF_BS_HI 20480
#define OFF_BS_LO 37376
#define GEMM_SMEM 54272

#define GEMM_BLOCKS ((N_NODES + TILE_M - 1) / TILE_M)        // 782
#define SCAT_BLOCKS ((N_EDGES + 511) / 512)                  // 3125

__global__ __launch_bounds__(512)
void gemm_scatter_kernel(const float* __restrict__ X,
                         const float* __restrict__ Wn,
                         const float* __restrict__ Ws,
                         float* __restrict__ out,
                         const int* __restrict__ src,
                         const int* __restrict__ dst) {
    // ---------------- scatter partition ----------------
    if (blockIdx.x >= GEMM_BLOCKS) {
        const int e = (blockIdx.x - GEMM_BLOCKS) * 512 + threadIdx.x;
        if (e < N_EDGES) {
            const int d = dst[e];
            const int pos = atomicAdd(&g_cursor[d], 1);
            g_list[pos] = ((unsigned long long)(unsigned)e << 32) | (unsigned)src[e];
        }
        return;
    }

    // ---------------- GEMM partition ----------------
    extern __shared__ char smem[];
    __nv_bfloat16* As_hi = (__nv_bfloat16*)(smem + OFF_AS_HI);
    __nv_bfloat16* As_lo = (__nv_bfloat16*)(smem + OFF_AS_LO);
    __nv_bfloat16* Bs_hi = (__nv_bfloat16*)(smem + OFF_BS_HI);
    __nv_bfloat16* Bs_lo = (__nv_bfloat16*)(smem + OFF_BS_LO);

    const int tid  = threadIdx.x;
    const int wid  = tid >> 5;
    const int lane = tid & 31;
    const int warp_m = wid & 3;
    const int warp_n = wid >> 2;
    const int rowBase = blockIdx.x * TILE_M;

    const int arow  = tid >> 2;
    const int acol  = (tid & 3) * 8;
    const int agrow = rowBase + arow;
    const int brow = tid >> 4;
    const int bcol = (tid & 15) * 16;
    const float* __restrict__ Wsel = (bcol < 128) ? Wn : Ws;
    const int wcol = bcol & 127;

    wmma::fragment<wmma::accumulator, 16, 16, 16, float> acc[2][4];
    #pragma unroll
    for (int m = 0; m < 2; m++)
        #pragma unroll
        for (int n = 0; n < 4; n++)
            wmma::fill_fragment(acc[m][n], 0.0f);

    float4 pa[2], pb[4];
    #pragma unroll
    for (int j = 0; j < 2; j++)
        pa[j] = (agrow < N_NODES)
              ? *(const float4*)(X + (size_t)agrow * D_IN + acol + j * 4)
              : make_float4(0.f, 0.f, 0.f, 0.f);
    #pragma unroll
    for (int j = 0; j < 4; j++)
        pb[j] = *(const float4*)(Wsel + (size_t)brow * D_OUT + wcol + j * 4);

    for (int c = 0; c < NCHUNK; ++c) {
        #pragma unroll
        for (int j = 0; j < 2; j++) {
            __nv_bfloat16 h0,h1,h2,h3,l0,l1,l2,l3;
            split_bf16(pa[j].x, h0, l0); split_bf16(pa[j].y, h1, l1);
            split_bf16(pa[j].z, h2, l2); split_bf16(pa[j].w, h3, l3);
            const int o = arow * LDA + acol + j * 4;
            *(uint2*)(As_hi + o) = make_uint2(pack_bf16(h0,h1), pack_bf16(h2,h3));
            *(uint2*)(As_lo + o) = make_uint2(pack_bf16(l0,l1), pack_bf16(l2,l3));
        }
        #pragma unroll
        for (int j = 0; j < 4; j++) {
            __nv_bfloat16 h0,h1,h2,h3,l0,l1,l2,l3;
            split_bf16(pb[j].x, h0, l0); split_bf16(pb[j].y, h1, l1);
            split_bf16(pb[j].z, h2, l2); split_bf16(pb[j].w, h3, l3);
            const int o = brow * LDB + bcol + j * 4;
            *(uint2*)(Bs_hi + o) = make_uint2(pack_bf16(h0,h1), pack_bf16(h2,h3));
            *(uint2*)(Bs_lo + o) = make_uint2(pack_bf16(l0,l1), pack_bf16(l2,l3));
        }
        __syncthreads();

        if (c + 1 < NCHUNK) {
            const int k0 = (c + 1) * KC;
            #pragma unroll
            for (int j = 0; j < 2; j++)
                pa[j] = (agrow < N_NODES)
                      ? *(const float4*)(X + (size_t)agrow * D_IN + k0 + acol + j * 4)
                      : make_float4(0.f, 0.f, 0.f, 0.f);
            #pragma unroll
            for (int j = 0; j < 4; j++)
                pb[j] = *(const float4*)(Wsel + (size_t)(k0 + brow) * D_OUT + wcol + j * 4);
        }

        #pragma unroll
        for (int ks = 0; ks < KC / 16; ks++) {
            wmma::fragment<wmma::matrix_a, 16, 16, 16, __nv_bfloat16, wmma::row_major> a_hi[2], a_lo[2];
            #pragma unroll
            for (int m = 0; m < 2; m++) {
                wmma::load_matrix_sync(a_hi[m], As_hi + (warp_m * 32 + m * 16) * LDA + ks * 16, LDA);
                wmma::load_matrix_sync(a_lo[m], As_lo + (warp_m * 32 + m * 16) * LDA + ks * 16, LDA);
            }
            #pragma unroll
            for (int n = 0; n < 4; n++) {
                wmma::fragment<wmma::matrix_b, 16, 16, 16, __nv_bfloat16, wmma::row_major> b_hi, b_lo;
                wmma::load_matrix_sync(b_hi, Bs_hi + (ks * 16) * LDB + warp_n * 64 + n * 16, LDB);
                wmma::load_matrix_sync(b_lo, Bs_lo + (ks * 16) * LDB + warp_n * 64 + n * 16, LDB);
                #pragma unroll
                for (int m = 0; m < 2; m++) {
                    wmma::mma_sync(acc[m][n], a_hi[m], b_hi, acc[m][n]);
                    wmma::mma_sync(acc[m][n], a_hi[m], b_lo, acc[m][n]);
                    wmma::mma_sync(acc[m][n], a_lo[m], b_hi, acc[m][n]);
                }
            }
        }
        __syncthreads();
    }

    // ---- Epilogue: cols 0-127 -> g_Hb (bf16, staged), 128-255 -> out (fp32) ----
    const bool fullTile = (rowBase + TILE_M <= N_NODES);
    float* stage = (float*)smem + wid * 256;   // per-warp 1KB (smem free after loop)
    #pragma unroll
    for (int m = 0; m < 2; m++)
        #pragma unroll
        for (int n = 0; n < 4; n++) {
            const int row = rowBase + warp_m * 32 + m * 16;
            const int col = warp_n * 64 + n * 16;
            if (col < 128) {
                // stage fp32 -> convert -> bf16 global
                wmma::store_matrix_sync(stage, acc[m][n], 16, wmma::mem_row_major);
                __syncwarp();
                const int r  = lane >> 1;
                const int cc = (lane & 1) * 8;
                const int grow = row + r;
                if (grow < N_NODES) {
                    float4 a = *(float4*)(stage + r * 16 + cc + 0);
                    float4 b2 = *(float4*)(stage + r * 16 + cc + 4);
                    uint4 v = make_uint4(
                        pack_bf16(__float2bfloat16(a.x),  __float2bfloat16(a.y)),
                        pack_bf16(__float2bfloat16(a.z),  __float2bfloat16(a.w)),
                        pack_bf16(__float2bfloat16(b2.x), __float2bfloat16(b2.y)),
                        pack_bf16(__float2bfloat16(b2.z), __float2bfloat16(b2.w)));
                    *(uint4*)(g_Hb + (size_t)grow * D_OUT + col + cc) = v;
                }
                __syncwarp();
            } else if (fullTile) {
                wmma::store_matrix_sync(out + (size_t)row * D_OUT + (col - 128),
                                        acc[m][n], D_OUT, wmma::mem_row_major);
            } else {
                wmma::store_matrix_sync(stage, acc[m][n], 16, wmma::mem_row_major);
                __syncwarp();
                const int r  = lane >> 1;
                const int cc = (lane & 1) * 8;
                const int grow = row + r;
                if (grow < N_NODES) {
                    float* p = out + (size_t)grow * D_OUT + (col - 128) + cc;
                    *(float4*)(p + 0) = *(float4*)(stage + r * 16 + cc + 0);
                    *(float4*)(p + 4) = *(float4*)(stage + r * 16 + cc + 4);
                }
                __syncwarp();
            }
        }
}

// ---------------------------------------------------------------------------
// Aggregate: one warp per dst node (grid-stride). Atomic-free, 8-edge unroll.
// g_Hb gathers are bf16 (8B per lane). W_edge in shared memory.
//   out[d] += bias + ( sum_e H[src_e] + (sum_e Xe_e) @ We ) / deg[d]
// ---------------------------------------------------------------------------
__device__ __forceinline__ void acc_bf16x4(float4& h, uint2 u) {
    const float2 a = __bfloat1622float2(*reinterpret_cast<__nv_bfloat162*>(&u.x));
    const float2 b = __bfloat1622float2(*reinterpret_cast<__nv_bfloat162*>(&u.y));
    h.x += a.x; h.y += a.y; h.z += b.x; h.w += b.y;
}

__global__ __launch_bounds__(256, 4)
void aggregate_kernel(const float* __restrict__ Xe,
                      const float* __restrict__ We,    // [16][128]
                      const float* __restrict__ bias,
                      float* __restrict__ out) {
    __shared__ float4 sW[D_EDGE][32];   // [k][lane], 8KB

    const int tid  = threadIdx.x;
    const int lane = tid & 31;
    const int col  = lane * 4;

    for (int i = tid; i < D_EDGE * 32; i += 256) {
        const int k = i >> 5, l = i & 31;
        sW[k][l] = *(const float4*)(We + k * D_OUT + l * 4);
    }
    __syncthreads();

    const float4 b = *(const float4*)(bias + col);

    const int warpId = (blockIdx.x * blockDim.x + tid) >> 5;
    const int nWarps = (gridDim.x * blockDim.x) >> 5;

    for (int d = warpId; d < N_NODES; d += nWarps) {
        const int start = g_off[d];
        const int c     = g_deg[d];

        float4 h = make_float4(0.f, 0.f, 0.f, 0.f);
        float xacc0 = 0.f, xacc1 = 0.f, xacc2 = 0.f, xacc3 = 0.f;

        int i = 0;
        for (; i + 8 <= c; i += 8) {
            unsigned long long pe[8];
            #pragma unroll
            for (int j = 0; j < 8; j++) pe[j] = g_list[start + i + j];

            uint2 hu[8];
            #pragma unroll
            for (int j = 0; j < 8; j++)
                hu[j] = *(const uint2*)(g_Hb + (size_t)(unsigned)(pe[j] & 0xFFFFFFFFu) * D_OUT + col);

            const int eA = (lane < 16) ? (int)(pe[0] >> 32) : (int)(pe[1] >> 32);
            const int eB = (lane < 16) ? (int)(pe[2] >> 32) : (int)(pe[3] >> 32);
            const int eC = (lane < 16) ? (int)(pe[4] >> 32) : (int)(pe[5] >> 32);
            const int eD = (lane < 16) ? (int)(pe[6] >> 32) : (int)(pe[7] >> 32);
            const int xl = lane & 15;
            xacc0 += Xe[(size_t)eA * D_EDGE + xl];
            xacc1 += Xe[(size_t)eB * D_EDGE + xl];
            xacc2 += Xe[(size_t)eC * D_EDGE + xl];
            xacc3 += Xe[(size_t)eD * D_EDGE + xl];

            #pragma unroll
            for (int j = 0; j < 8; j++) acc_bf16x4(h, hu[j]);
        }
        for (; i + 2 <= c; i += 2) {
            const unsigned long long pe0 = g_list[start + i + 0];
            const unsigned long long pe1 = g_list[start + i + 1];
            const uint2 h0 = *(const uint2*)(g_Hb + (size_t)(unsigned)(pe0 & 0xFFFFFFFFu) * D_OUT + col);
            const uint2 h1 = *(const uint2*)(g_Hb + (size_t)(unsigned)(pe1 & 0xFFFFFFFFu) * D_OUT + col);
            const int e = (lane < 16) ? (int)(pe0 >> 32) : (int)(pe1 >> 32);
            xacc0 += Xe[(size_t)e * D_EDGE + (lane & 15)];
            acc_bf16x4(h, h0);
            acc_bf16x4(h, h1);
        }
        if (i < c) {
            const unsigned long long pe = g_list[start + i];
            const uint2 hv = *(const uint2*)(g_Hb + (size_t)(unsigned)(pe & 0xFFFFFFFFu) * D_OUT + col);
            acc_bf16x4(h, hv);
            if (lane < 16) xacc0 += Xe[(size_t)(int)(pe >> 32) * D_EDGE + lane];
        }

        float4 o = *(const float4*)(out + (size_t)d * D_OUT + col);
        o.x += b.x; o.y += b.y; o.z += b.z; o.w += b.w;

        if (c > 0) {
            float4 p = make_float4(0.f, 0.f, 0.f, 0.f);
            #pragma unroll
            for (int k = 0; k < D_EDGE; k++) {
                const float xk = (__shfl_sync(0xFFFFFFFFu, xacc0, k) +
                                  __shfl_sync(0xFFFFFFFFu, xacc0, k + 16)) +
                                 (__shfl_sync(0xFFFFFFFFu, xacc1, k) +
                                  __shfl_sync(0xFFFFFFFFu, xacc1, k + 16)) +
                                 (__shfl_sync(0xFFFFFFFFu, xacc2, k) +
                                  __shfl_sync(0xFFFFFFFFu, xacc2, k + 16)) +
                                 (__shfl_sync(0xFFFFFFFFu, xacc3, k) +
                                  __shfl_sync(0xFFFFFFFFu, xacc3, k + 16));
                const float4 wk = sW[k][lane];
                p.x = fmaf(xk, wk.x, p.x);
                p.y = fmaf(xk, wk.y, p.y);
                p.z = fmaf(xk, wk.z, p.z);
                p.w = fmaf(xk, wk.w, p.w);
            }
            const float inv = 1.0f / (float)c;
            o.x = fmaf(h.x + p.x, inv, o.x);
            o.y = fmaf(h.y + p.y, inv, o.y);
            o.z = fmaf(h.z + p.z, inv, o.z);
            o.w = fmaf(h.w + p.w, inv, o.w);
        }
        *(float4*)(out + (size_t)d * D_OUT + col) = o;
    }
}

// ---------------------------------------------------------------------------
// Launch
// ---------------------------------------------------------------------------
extern "C" void kernel_launch(void* const* d_in, const int* in_sizes, int n_in,
                              void* d_out, int out_size) {
    const float* X    = (const float*)d_in[0];
    const float* Xe   = (const float*)d_in[1];
    const float* Wn   = (const float*)d_in[2];
    const float* Ws   = (const float*)d_in[3];
    const float* bias = (const float*)d_in[4];
    const float* We   = (const float*)d_in[5];
    const int*   src  = (const int*)d_in[6];
    const int*   dst  = (const int*)d_in[7];
    float*       out  = (float*)d_out;

    cudaFuncSetAttribute(gemm_scatter_kernel,
                         cudaFuncAttributeMaxDynamicSharedMemorySize, GEMM_SMEM);

    // 1) zero degree array + scan-base counter (memset node, no kernel)
    void* degAddr = nullptr;
    cudaGetSymbolAddress(&degAddr, g_deg);
    cudaMemsetAsync(degAddr, 0, (N_NODES + 1) * sizeof(int));

    // 2) histogram of dst (4 edges per thread)
    hist_kernel<<<(N_EDGES / 4 + 255) / 256, 256>>>(dst);

    // 3) one-shot scan (block scan + atomic base grab)
    scan_kernel<<<SCAN_NB, SCAN_BLK>>>();

    // 4) fused: node GEMM (g_Hb = bf16(X@Wn) ; out = X@Ws) + CSR scatter
    gemm_scatter_kernel<<<GEMM_BLOCKS + SCAT_BLOCKS, 512, GEMM_SMEM>>>(
        X, Wn, Ws, out, src, dst);

    // 5) gather aggregation (fuses mean, edge projection, bias, final combine)
    aggregate_kernel<<<2048, 256>>>(Xe, We, bias, out);
}

// round 9
// speedup vs baseline: 3.9854x; 1.1277x over previous
#include <cuda_runtime.h>
#include <cuda_bf16.h>
#include <mma.h>
#include <cstdint>

using namespace nvcuda;

#define N_NODES 100000
#define N_EDGES 1600000
#define D_IN    256
#define D_EDGE  16
#define D_OUT   128

#define SCAN_BLK  1024
#define SCAN_NB   ((N_NODES + SCAN_BLK - 1) / SCAN_BLK)   // 98

// Scratch (allocation-free rule: __device__ globals)
__device__ __nv_bfloat16      g_Hb[(size_t)N_NODES * D_OUT]; // X @ W_neigh (bf16)
__device__ __nv_bfloat16      g_Whi[D_IN * 256];             // [k][c]: c<128 Wn, else Ws (hi)
__device__ __nv_bfloat16      g_Wlo[D_IN * 256];             // (lo)
__device__ int                g_deg[N_NODES + 1];            // in-degree; [N_NODES] = scan base
__device__ int                g_off[N_NODES];                // CSR offsets
__device__ int                g_cursor[N_NODES];             // scatter cursors
__device__ unsigned long long g_list[N_EDGES];               // packed (e*16)<<32 | (s*128)

__device__ __forceinline__ uint32_t pack_bf16(__nv_bfloat16 a, __nv_bfloat16 b) {
    __nv_bfloat162 t(a, b);
    return *reinterpret_cast<uint32_t*>(&t);
}
__device__ __forceinline__ void split_bf16(float x, __nv_bfloat16& hi, __nv_bfloat16& lo) {
    hi = __float2bfloat16(x);
    lo = __float2bfloat16(x - __bfloat162float(hi));
}

// ---------------------------------------------------------------------------
// One-time W pre-split: [Wn|Ws] fp32 -> bf16 hi/lo (removes 782x redundant
// per-block conversion work from the GEMM).
// ---------------------------------------------------------------------------
__global__ __launch_bounds__(256)
void wsplit_kernel(const float* __restrict__ Wn, const float* __restrict__ Ws) {
    const int i = blockIdx.x * blockDim.x + threadIdx.x;   // 16384 threads, 4 elems each
    const int k = i >> 6;            // 0..255
    const int c = (i & 63) * 4;      // 0..252
    const float4 v = (c < 128)
                   ? *(const float4*)(Wn + (size_t)k * D_OUT + c)
                   : *(const float4*)(Ws + (size_t)k * D_OUT + (c - 128));
    __nv_bfloat16 h0,h1,h2,h3,l0,l1,l2,l3;
    split_bf16(v.x, h0, l0); split_bf16(v.y, h1, l1);
    split_bf16(v.z, h2, l2); split_bf16(v.w, h3, l3);
    *(uint2*)(g_Whi + k * 256 + c) = make_uint2(pack_bf16(h0,h1), pack_bf16(h2,h3));
    *(uint2*)(g_Wlo + k * 256 + c) = make_uint2(pack_bf16(l0,l1), pack_bf16(l2,l3));
}

// ---------------------------------------------------------------------------
// CSR: histogram (int4 loads, 4 edges per thread)
// ---------------------------------------------------------------------------
__global__ void hist_kernel(const int* __restrict__ dst) {
    int i = blockIdx.x * blockDim.x + threadIdx.x;
    if (i * 4 + 3 < N_EDGES) {
        const int4 d4 = *(const int4*)(dst + i * 4);
        atomicAdd(&g_deg[d4.x], 1);
        atomicAdd(&g_deg[d4.y], 1);
        atomicAdd(&g_deg[d4.z], 1);
        atomicAdd(&g_deg[d4.w], 1);
    } else {
        for (int e = i * 4; e < N_EDGES; ++e)
            atomicAdd(&g_deg[dst[e]], 1);
    }
}

// ---------------------------------------------------------------------------
// CSR: one-shot scan. Block-local Hillis-Steele + atomic base grab.
// ---------------------------------------------------------------------------
__global__ __launch_bounds__(SCAN_BLK)
void scan_kernel() {
    __shared__ int s[SCAN_BLK];
    __shared__ int base;
    const int t = threadIdx.x;
    const int i = blockIdx.x * SCAN_BLK + t;
    const int d = (i < N_NODES) ? g_deg[i] : 0;
    s[t] = d;
    __syncthreads();
    #pragma unroll
    for (int off = 1; off < SCAN_BLK; off <<= 1) {
        int v = (t >= off) ? s[t - off] : 0;
        __syncthreads();
        s[t] += v;
        __syncthreads();
    }
    if (t == SCAN_BLK - 1) base = atomicAdd(&g_deg[N_NODES], s[t]);
    __syncthreads();
    if (i < N_NODES) {
        const int o = base + s[t] - d;
        g_off[i] = o;
        g_cursor[i] = o;
    }
}

// ---------------------------------------------------------------------------
// Fused launch: blocks [0, GEMM_BLOCKS) run the wmma node GEMM,
// blocks [GEMM_BLOCKS, +SCAT_BLOCKS) run the CSR scatter (independent work).
// ---------------------------------------------------------------------------
#define TILE_M 128
#define KC     32
#define NCHUNK (D_IN / KC)   // 8
#define LDA    40            // As row stride (bf16), 80B
#define LDB    264           // Bs row stride (bf16), 528B
#define OFF_AS_HI 0
#define OFF_AS_LO 10240
#define OFF_BS_HI 20480
#define OFF_BS_LO 37376
#define GEMM_SMEM 54272

#define GEMM_BLOCKS ((N_NODES + TILE_M - 1) / TILE_M)        // 782
#define SCAT_BLOCKS ((N_EDGES + 511) / 512)                  // 3125

__global__ __launch_bounds__(512)
void gemm_scatter_kernel(const float* __restrict__ X,
                         float* __restrict__ out,
                         const int* __restrict__ src,
                         const int* __restrict__ dst) {
    // ---------------- scatter partition ----------------
    if (blockIdx.x >= GEMM_BLOCKS) {
        const int e = (blockIdx.x - GEMM_BLOCKS) * 512 + threadIdx.x;
        if (e < N_EDGES) {
            const int d = dst[e];
            const int pos = atomicAdd(&g_cursor[d], 1);
            // pre-multiplied offsets: hi = e*D_EDGE (Xe row), lo = s*D_OUT (H row)
            g_list[pos] = ((unsigned long long)(unsigned)(e * D_EDGE) << 32)
                        | (unsigned)(src[e] * D_OUT);
        }
        return;
    }

    // ---------------- GEMM partition ----------------
    extern __shared__ char smem[];
    __nv_bfloat16* As_hi = (__nv_bfloat16*)(smem + OFF_AS_HI);
    __nv_bfloat16* As_lo = (__nv_bfloat16*)(smem + OFF_AS_LO);
    __nv_bfloat16* Bs_hi = (__nv_bfloat16*)(smem + OFF_BS_HI);
    __nv_bfloat16* Bs_lo = (__nv_bfloat16*)(smem + OFF_BS_LO);

    const int tid  = threadIdx.x;
    const int wid  = tid >> 5;
    const int lane = tid & 31;
    const int warp_m = wid & 3;
    const int warp_n = wid >> 2;
    const int rowBase = blockIdx.x * TILE_M;

    const int arow  = tid >> 2;
    const int acol  = (tid & 3) * 8;
    const int agrow = rowBase + arow;
    const int brow = tid >> 4;           // 0..31
    const int bcol = (tid & 15) * 16;    // 0..240

    wmma::fragment<wmma::accumulator, 16, 16, 16, float> acc[2][4];
    #pragma unroll
    for (int m = 0; m < 2; m++)
        #pragma unroll
        for (int n = 0; n < 4; n++)
            wmma::fill_fragment(acc[m][n], 0.0f);

    float4 pa[2];
    uint4  pbh[2], pbl[2];
    #pragma unroll
    for (int j = 0; j < 2; j++)
        pa[j] = (agrow < N_NODES)
              ? *(const float4*)(X + (size_t)agrow * D_IN + acol + j * 4)
              : make_float4(0.f, 0.f, 0.f, 0.f);
    #pragma unroll
    for (int j = 0; j < 2; j++) {
        pbh[j] = *(const uint4*)(g_Whi + brow * 256 + bcol + j * 8);
        pbl[j] = *(const uint4*)(g_Wlo + brow * 256 + bcol + j * 8);
    }

    for (int c = 0; c < NCHUNK; ++c) {
        #pragma unroll
        for (int j = 0; j < 2; j++) {
            __nv_bfloat16 h0,h1,h2,h3,l0,l1,l2,l3;
            split_bf16(pa[j].x, h0, l0); split_bf16(pa[j].y, h1, l1);
            split_bf16(pa[j].z, h2, l2); split_bf16(pa[j].w, h3, l3);
            const int o = arow * LDA + acol + j * 4;
            *(uint2*)(As_hi + o) = make_uint2(pack_bf16(h0,h1), pack_bf16(h2,h3));
            *(uint2*)(As_lo + o) = make_uint2(pack_bf16(l0,l1), pack_bf16(l2,l3));
        }
        #pragma unroll
        for (int j = 0; j < 2; j++) {
            const int o = brow * LDB + bcol + j * 8;
            *(uint4*)(Bs_hi + o) = pbh[j];
            *(uint4*)(Bs_lo + o) = pbl[j];
        }
        __syncthreads();

        if (c + 1 < NCHUNK) {
            const int k0 = (c + 1) * KC;
            #pragma unroll
            for (int j = 0; j < 2; j++)
                pa[j] = (agrow < N_NODES)
                      ? *(const float4*)(X + (size_t)agrow * D_IN + k0 + acol + j * 4)
                      : make_float4(0.f, 0.f, 0.f, 0.f);
            #pragma unroll
            for (int j = 0; j < 2; j++) {
                pbh[j] = *(const uint4*)(g_Whi + (k0 + brow) * 256 + bcol + j * 8);
                pbl[j] = *(const uint4*)(g_Wlo + (k0 + brow) * 256 + bcol + j * 8);
            }
        }

        #pragma unroll
        for (int ks = 0; ks < KC / 16; ks++) {
            wmma::fragment<wmma::matrix_a, 16, 16, 16, __nv_bfloat16, wmma::row_major> a_hi[2], a_lo[2];
            #pragma unroll
            for (int m = 0; m < 2; m++) {
                wmma::load_matrix_sync(a_hi[m], As_hi + (warp_m * 32 + m * 16) * LDA + ks * 16, LDA);
                wmma::load_matrix_sync(a_lo[m], As_lo + (warp_m * 32 + m * 16) * LDA + ks * 16, LDA);
            }
            #pragma unroll
            for (int n = 0; n < 4; n++) {
                wmma::fragment<wmma::matrix_b, 16, 16, 16, __nv_bfloat16, wmma::row_major> b_hi, b_lo;
                wmma::load_matrix_sync(b_hi, Bs_hi + (ks * 16) * LDB + warp_n * 64 + n * 16, LDB);
                wmma::load_matrix_sync(b_lo, Bs_lo + (ks * 16) * LDB + warp_n * 64 + n * 16, LDB);
                #pragma unroll
                for (int m = 0; m < 2; m++) {
                    wmma::mma_sync(acc[m][n], a_hi[m], b_hi, acc[m][n]);
                    wmma::mma_sync(acc[m][n], a_hi[m], b_lo, acc[m][n]);
                    wmma::mma_sync(acc[m][n], a_lo[m], b_hi, acc[m][n]);
                }
            }
        }
        __syncthreads();
    }

    // ---- Epilogue: cols 0-127 -> g_Hb (bf16, staged), 128-255 -> out (fp32) ----
    const bool fullTile = (rowBase + TILE_M <= N_NODES);
    float* stage = (float*)smem + wid * 256;   // per-warp 1KB (smem free after loop)
    #pragma unroll
    for (int m = 0; m < 2; m++)
        #pragma unroll
        for (int n = 0; n < 4; n++) {
            const int row = rowBase + warp_m * 32 + m * 16;
            const int col = warp_n * 64 + n * 16;
            if (col < 128) {
                wmma::store_matrix_sync(stage, acc[m][n], 16, wmma::mem_row_major);
                __syncwarp();
                const int r  = lane >> 1;
                const int cc = (lane & 1) * 8;
                const int grow = row + r;
                if (grow < N_NODES) {
                    float4 a = *(float4*)(stage + r * 16 + cc + 0);
                    float4 b2 = *(float4*)(stage + r * 16 + cc + 4);
                    uint4 v = make_uint4(
                        pack_bf16(__float2bfloat16(a.x),  __float2bfloat16(a.y)),
                        pack_bf16(__float2bfloat16(a.z),  __float2bfloat16(a.w)),
                        pack_bf16(__float2bfloat16(b2.x), __float2bfloat16(b2.y)),
                        pack_bf16(__float2bfloat16(b2.z), __float2bfloat16(b2.w)));
                    *(uint4*)(g_Hb + (size_t)grow * D_OUT + col + cc) = v;
                }
                __syncwarp();
            } else if (fullTile) {
                wmma::store_matrix_sync(out + (size_t)row * D_OUT + (col - 128),
                                        acc[m][n], D_OUT, wmma::mem_row_major);
            } else {
                wmma::store_matrix_sync(stage, acc[m][n], 16, wmma::mem_row_major);
                __syncwarp();
                const int r  = lane >> 1;
                const int cc = (lane & 1) * 8;
                const int grow = row + r;
                if (grow < N_NODES) {
                    float* p = out + (size_t)grow * D_OUT + (col - 128) + cc;
                    *(float4*)(p + 0) = *(float4*)(stage + r * 16 + cc + 0);
                    *(float4*)(p + 4) = *(float4*)(stage + r * 16 + cc + 4);
                }
                __syncwarp();
            }
        }
}

// ---------------------------------------------------------------------------
// Aggregate: one warp per dst node (grid-stride). Atomic-free, 8-edge unroll.
// g_list holds pre-multiplied offsets; epilogue uses 32 shuffles (not 128).
// ---------------------------------------------------------------------------
__device__ __forceinline__ void acc_bf16x4(float4& h, uint2 u) {
    const float2 a = __bfloat1622float2(*reinterpret_cast<__nv_bfloat162*>(&u.x));
    const float2 b = __bfloat1622float2(*reinterpret_cast<__nv_bfloat162*>(&u.y));
    h.x += a.x; h.y += a.y; h.z += b.x; h.w += b.y;
}

__global__ __launch_bounds__(256, 4)
void aggregate_kernel(const float* __restrict__ Xe,
                      const float* __restrict__ We,    // [16][128]
                      const float* __restrict__ bias,
                      float* __restrict__ out) {
    __shared__ float4 sW[D_EDGE][32];   // [k][lane], 8KB

    const int tid  = threadIdx.x;
    const int lane = tid & 31;
    const int col  = lane * 4;

    for (int i = tid; i < D_EDGE * 32; i += 256) {
        const int k = i >> 5, l = i & 31;
        sW[k][l] = *(const float4*)(We + k * D_OUT + l * 4);
    }
    __syncthreads();

    const float4 b = *(const float4*)(bias + col);

    const int warpId = (blockIdx.x * blockDim.x + tid) >> 5;
    const int nWarps = (gridDim.x * blockDim.x) >> 5;

    for (int d = warpId; d < N_NODES; d += nWarps) {
        const int start = g_off[d];
        const int c     = g_deg[d];

        float4 h = make_float4(0.f, 0.f, 0.f, 0.f);
        float xacc0 = 0.f, xacc1 = 0.f, xacc2 = 0.f, xacc3 = 0.f;
        const int xl = lane & 15;

        int i = 0;
        for (; i + 8 <= c; i += 8) {
            unsigned long long pe[8];
            #pragma unroll
            for (int j = 0; j < 8; j++) pe[j] = g_list[start + i + j];

            uint2 hu[8];
            #pragma unroll
            for (int j = 0; j < 8; j++)
                hu[j] = *(const uint2*)(g_Hb + (unsigned)pe[j] + col);

            const unsigned eA = (lane < 16) ? (unsigned)(pe[0] >> 32) : (unsigned)(pe[1] >> 32);
            const unsigned eB = (lane < 16) ? (unsigned)(pe[2] >> 32) : (unsigned)(pe[3] >> 32);
            const unsigned eC = (lane < 16) ? (unsigned)(pe[4] >> 32) : (unsigned)(pe[5] >> 32);
            const unsigned eD = (lane < 16) ? (unsigned)(pe[6] >> 32) : (unsigned)(pe[7] >> 32);
            xacc0 += Xe[eA + xl];
            xacc1 += Xe[eB + xl];
            xacc2 += Xe[eC + xl];
            xacc3 += Xe[eD + xl];

            #pragma unroll
            for (int j = 0; j < 8; j++) acc_bf16x4(h, hu[j]);
        }
        for (; i + 2 <= c; i += 2) {
            const unsigned long long pe0 = g_list[start + i + 0];
            const unsigned long long pe1 = g_list[start + i + 1];
            const uint2 h0 = *(const uint2*)(g_Hb + (unsigned)pe0 + col);
            const uint2 h1 = *(const uint2*)(g_Hb + (unsigned)pe1 + col);
            const unsigned e = (lane < 16) ? (unsigned)(pe0 >> 32) : (unsigned)(pe1 >> 32);
            xacc0 += Xe[e + xl];
            acc_bf16x4(h, h0);
            acc_bf16x4(h, h1);
        }
        if (i < c) {
            const unsigned long long pe = g_list[start + i];
            const uint2 hv = *(const uint2*)(g_Hb + (unsigned)pe + col);
            acc_bf16x4(h, hv);
            if (lane < 16) xacc0 += Xe[(unsigned)(pe >> 32) + xl];
        }

        float4 o = *(const float4*)(out + (size_t)d * D_OUT + col);
        o.x += b.x; o.y += b.y; o.z += b.z; o.w += b.w;

        if (c > 0) {
            // combine the 4 partial accumulators first -> 32 shuffles total
            const float xs = (xacc0 + xacc1) + (xacc2 + xacc3);
            float4 p = make_float4(0.f, 0.f, 0.f, 0.f);
            #pragma unroll
            for (int k = 0; k < D_EDGE; k++) {
                const float xk = __shfl_sync(0xFFFFFFFFu, xs, k) +
                                 __shfl_sync(0xFFFFFFFFu, xs, k + 16);
                const float4 wk = sW[k][lane];
                p.x = fmaf(xk, wk.x, p.x);
                p.y = fmaf(xk, wk.y, p.y);
                p.z = fmaf(xk, wk.z, p.z);
                p.w = fmaf(xk, wk.w, p.w);
            }
            const float inv = 1.0f / (float)c;
            o.x = fmaf(h.x + p.x, inv, o.x);
            o.y = fmaf(h.y + p.y, inv, o.y);
            o.z = fmaf(h.z + p.z, inv, o.z);
            o.w = fmaf(h.w + p.w, inv, o.w);
        }
        *(float4*)(out + (size_t)d * D_OUT + col) = o;
    }
}

// ---------------------------------------------------------------------------
// Launch
// ---------------------------------------------------------------------------
extern "C" void kernel_launch(void* const* d_in, const int* in_sizes, int n_in,
                              void* d_out, int out_size) {
    const float* X    = (const float*)d_in[0];
    const float* Xe   = (const float*)d_in[1];
    const float* Wn   = (const float*)d_in[2];
    const float* Ws   = (const float*)d_in[3];
    const float* bias = (const float*)d_in[4];
    const float* We   = (const float*)d_in[5];
    const int*   src  = (const int*)d_in[6];
    const int*   dst  = (const int*)d_in[7];
    float*       out  = (float*)d_out;

    cudaFuncSetAttribute(gemm_scatter_kernel,
                         cudaFuncAttributeMaxDynamicSharedMemorySize, GEMM_SMEM);

    // 1) zero degree array + scan-base counter (memset node, no kernel)
    void* degAddr = nullptr;
    cudaGetSymbolAddress(&degAddr, g_deg);
    cudaMemsetAsync(degAddr, 0, (N_NODES + 1) * sizeof(int));

    // 2) one-time W pre-split (bf16 hi/lo)
    wsplit_kernel<<<64, 256>>>(Wn, Ws);

    // 3) histogram of dst (4 edges per thread)
    hist_kernel<<<(N_EDGES / 4 + 255) / 256, 256>>>(dst);

    // 4) one-shot scan (block scan + atomic base grab)
    scan_kernel<<<SCAN_NB, SCAN_BLK>>>();

    // 5) fused: node GEMM (g_Hb = bf16(X@Wn) ; out = X@Ws) + CSR scatter
    gemm_scatter_kernel<<<GEMM_BLOCKS + SCAT_BLOCKS, 512, GEMM_SMEM>>>(
        X, out, src, dst);

    // 6) gather aggregation (fuses mean, edge projection, bias, final combine)
    aggregate_kernel<<<2048, 256>>>(Xe, We, bias, out);
}